// round 7
// baseline (speedup 1.0000x reference)
#include <cuda_runtime.h>
#include <math.h>

#define Tsz 256
#define Hsz 256

__device__ float g_h1[(size_t)256*256*512];
__device__ float g_hb0[2][2][256*256];
__device__ float g_hb1[2][256*256];
__device__ float g_h2f[256*256];
__device__ float g_h2b[256*256];
__device__ unsigned g_fl0[128], g_fl1[128], g_ex0, g_ex1;

typedef unsigned long long u64;
__device__ __forceinline__ u64 ffma2(u64 a,u64 b,u64 c){u64 d;asm("fma.rn.f32x2 %0,%1,%2,%3;":"=l"(d):"l"(a),"l"(b),"l"(c));return d;}
__device__ __forceinline__ u64 dup2(float v){u64 d;asm("mov.b64 %0,{%1,%2};":"=l"(d):"f"(v),"f"(v));return d;}
__device__ __forceinline__ float lo2(u64 v){return __uint_as_float((unsigned)v);}
__device__ __forceinline__ float hi2(u64 v){return __uint_as_float((unsigned)(v>>32));}
__device__ __forceinline__ float sigm(float v){return 1.f/(1.f+__expf(-v));}
__device__ __forceinline__ float2 ldcg2(const float2* p){float2 v;
    asm volatile("ld.global.cg.v2.f32 {%0,%1},[%2];":"=f"(v.x),"=f"(v.y):"l"(p));return v;}

__device__ __forceinline__ void gbar(unsigned* fl,int lbid,int nb,unsigned tgt){
    __syncthreads();
    if(threadIdx.x==0){__threadfence();atomicExch(&fl[lbid],tgt);}
    int tid=threadIdx.x;
    for(;;){
        int ok=1;
        if(tid<nb){unsigned v;asm volatile("ld.global.cg.u32 %0,[%1];":"=r"(v):"l"(fl+tid));ok=(v>=tgt);}
        if(__syncthreads_and(ok))break;
    }
}

// ===== layer 0: 128 blocks = dir(2) x bt(4 of 64b) x jt(16 of 16j) ========
// thread = 2 b x 1 jp (2 j). Weights j-pair interleaved in smem, h via LDG.cg.
__global__ void __launch_bounds__(256,1) gru0(
    const float* __restrict__ x,const float* __restrict__ Wih0,
    const float* __restrict__ Whh0,const float* __restrict__ bih0,
    const float* __restrict__ bhh0)
{
    extern __shared__ __align__(16) u64 smu[];
    u64* wrz=smu;            // 1024 slots x 6 u64 (48B): (r_k,z_k,r_k1,z_k1,pad,pad)
    u64* wn2=smu+6144;       // 1024 slots x 2 u64: (n_k, n_k1)
    const int dir=blockIdx.x>>6, lb=blockIdx.x&63;
    const int bt=lb>>4, jt=lb&15, tid=threadIdx.x;
    const int tb=tid>>3, jp=tid&7;
    const int b0=bt*64+tb*2, b1=b0+1;
    const int j0=jt*16+2*jp, j1=j0+1;

    const float* Whh=Whh0+(size_t)dir*768*Hsz;
    for(int i=tid;i<1024;i+=256){
        int k2=i>>3, p=i&7, k0=2*k2;
        int J0=jt*16+2*p, J1=J0+1;
        #pragma unroll
        for(int kk=0;kk<2;kk++){
            float r0=Whh[(size_t)(0*256+J0)*256+k0+kk], r1=Whh[(size_t)(0*256+J1)*256+k0+kk];
            float z0=Whh[(size_t)(1*256+J0)*256+k0+kk], z1=Whh[(size_t)(1*256+J1)*256+k0+kk];
            float n0=Whh[(size_t)(2*256+J0)*256+k0+kk], n1=Whh[(size_t)(2*256+J1)*256+k0+kk];
            *(float2*)&wrz[(size_t)i*6+2*kk+0]=make_float2(r0,r1);
            *(float2*)&wrz[(size_t)i*6+2*kk+1]=make_float2(z0,z1);
            *(float2*)&wn2[(size_t)i*2+kk]=make_float2(n0,n1);
        }
    }
    // epilogue constants (j fixed per thread)
    const float* Wih=Wih0+(size_t)dir*768*4;
    const float4 wxr0=*(const float4*)&Wih[(0*256+j0)*4], wxr1=*(const float4*)&Wih[(0*256+j1)*4];
    const float4 wxz0=*(const float4*)&Wih[(1*256+j0)*4], wxz1=*(const float4*)&Wih[(1*256+j1)*4];
    const float4 wxn0=*(const float4*)&Wih[(2*256+j0)*4], wxn1=*(const float4*)&Wih[(2*256+j1)*4];
    const float* bi=bih0+dir*768; const float* bh=bhh0+dir*768;
    const float cr0=bi[j0],cr1=bi[j1],cz0=bi[256+j0],cz1=bi[256+j1],cn0=bi[512+j0],cn1=bi[512+j1];
    const float br0=bh[j0],br1=bh[j1],bz0=bh[256+j0],bz1=bh[256+j1],bn0=bh[512+j0],bn1=bh[512+j1];

    if(jt==0){float4 z4={0,0,0,0};float4* d=(float4*)&g_hb0[dir][0][bt*64*Hsz];
        for(int i=tid;i<64*Hsz/4;i+=256)d[i]=z4;}
    unsigned ph=1;
    gbar(g_fl0+dir*64,lb,64,ph++);

    for(int s=0;s<Tsz;s++){
        const int t=dir?255-s:s;
        const float* hp=g_hb0[dir][s&1];
        float* hn_=g_hb0[dir][(s&1)^1];
        const float2* xpa=(const float2*)&hp[b0*Hsz];
        const float2* xpb=(const float2*)&hp[b1*Hsz];
        float2 hpa=ldcg2((const float2*)&hp[b0*Hsz+j0]);
        float2 hpb=ldcg2((const float2*)&hp[b1*Hsz+j0]);
        float4 xva=((const float4*)x)[(size_t)b0*Tsz+t];
        float4 xvb=((const float4*)x)[(size_t)b1*Tsz+t];

        u64 arA=0,azA=0,anA=0,arB=0,azB=0,anB=0;
        #pragma unroll 8
        for(int k2=0;k2<128;k2++){
            float2 ha=ldcg2(&xpa[k2]), hb=ldcg2(&xpb[k2]);
            u64 a0=dup2(ha.x),a1=dup2(ha.y),c0=dup2(hb.x),c1=dup2(hb.y);
            const u64* sl=&wrz[(size_t)(k2*8+jp)*6];
            ulonglong2 rz0=*(const ulonglong2*)sl;
            ulonglong2 rz1=*(const ulonglong2*)(sl+2);
            ulonglong2 nn=*(const ulonglong2*)&wn2[(size_t)(k2*8+jp)*2];
            arA=ffma2(a0,rz0.x,arA); azA=ffma2(a0,rz0.y,azA); anA=ffma2(a0,nn.x,anA);
            arA=ffma2(a1,rz1.x,arA); azA=ffma2(a1,rz1.y,azA); anA=ffma2(a1,nn.y,anA);
            arB=ffma2(c0,rz0.x,arB); azB=ffma2(c0,rz0.y,azB); anB=ffma2(c0,nn.x,anB);
            arB=ffma2(c1,rz1.x,arB); azB=ffma2(c1,rz1.y,azB); anB=ffma2(c1,nn.y,anB);
        }
        #pragma unroll
        for(int bb=0;bb<2;bb++){
            float4 xv=bb?xvb:xva; float2 hpv=bb?hpb:hpa;
            u64 ar=bb?arB:arA, az=bb?azB:azA, an=bb?anB:anA;
            int bg=bb?b1:b0;
            float xr0=cr0+xv.x*wxr0.x+xv.y*wxr0.y+xv.z*wxr0.z+xv.w*wxr0.w;
            float xr1=cr1+xv.x*wxr1.x+xv.y*wxr1.y+xv.z*wxr1.z+xv.w*wxr1.w;
            float xz0=cz0+xv.x*wxz0.x+xv.y*wxz0.y+xv.z*wxz0.z+xv.w*wxz0.w;
            float xz1=cz1+xv.x*wxz1.x+xv.y*wxz1.y+xv.z*wxz1.z+xv.w*wxz1.w;
            float xn0=cn0+xv.x*wxn0.x+xv.y*wxn0.y+xv.z*wxn0.z+xv.w*wxn0.w;
            float xn1=cn1+xv.x*wxn1.x+xv.y*wxn1.y+xv.z*wxn1.z+xv.w*wxn1.w;
            float r0=sigm(xr0+lo2(ar)+br0), r1=sigm(xr1+hi2(ar)+br1);
            float z0=sigm(xz0+lo2(az)+bz0), z1=sigm(xz1+hi2(az)+bz1);
            float n0=tanhf(xn0+r0*(lo2(an)+bn0)), n1=tanhf(xn1+r1*(hi2(an)+bn1));
            float h0=(1.f-z0)*n0+z0*hpv.x, h1=(1.f-z1)*n1+z1*hpv.y;
            *(float2*)&hn_[bg*Hsz+j0]=make_float2(h0,h1);
            *(float2*)&g_h1[((size_t)bg*Tsz+t)*512+dir*Hsz+j0]=make_float2(h0,h1);
        }
        gbar(g_fl0+dir*64,lb,64,ph++);
    }
    if(tid==0){unsigned o=atomicAdd(&g_ex0,1u);
        if(o==127u){for(int i=0;i<128;i++)((volatile unsigned*)g_fl0)[i]=0;g_ex0=0;__threadfence();}}
}

// ===== layer 1: 128 blocks = bt(8 of 32b) x jt(16 of 16j) =================
// thread = 1 b x 1 jp (2 j). K=768: k<512 from g_h1 (__ldg), k>=512 hprev (.cg).
__global__ void __launch_bounds__(256,1) gru1(
    const float* __restrict__ Wih1,const float* __restrict__ Whh1,
    const float* __restrict__ bih1,const float* __restrict__ bhh1,int bwd)
{
    extern __shared__ __align__(16) u64 smu[];
    u64* wrz=smu;            // 3072 slots x 6 u64 (48B)
    u64* wn2=smu+18432;      // 3072 slots x 2 u64
    const int bt=blockIdx.x>>4, jt=blockIdx.x&15, tid=threadIdx.x;
    const int b=tid>>3, jp=tid&7;
    const int bg=bt*32+b;
    const int j0=jt*16+2*jp, j1=j0+1;
    const float* Wih=Wih1+(size_t)bwd*768*512;
    const float* Whh=Whh1+(size_t)bwd*768*Hsz;

    for(int i=tid;i<3072;i+=256){
        int k2=i>>3, p=i&7, k0=2*k2;
        int J0=jt*16+2*p, J1=J0+1;
        #pragma unroll
        for(int kk=0;kk<2;kk++){
            int k=k0+kk;
            float r0,r1,z0,z1,n0,n1;
            if(k<512){
                r0=Wih[(size_t)(0*256+J0)*512+k]; r1=Wih[(size_t)(0*256+J1)*512+k];
                z0=Wih[(size_t)(1*256+J0)*512+k]; z1=Wih[(size_t)(1*256+J1)*512+k];
                n0=Wih[(size_t)(2*256+J0)*512+k]; n1=Wih[(size_t)(2*256+J1)*512+k];
            }else{
                int kh=k-512;
                r0=Whh[(size_t)(0*256+J0)*256+kh]; r1=Whh[(size_t)(0*256+J1)*256+kh];
                z0=Whh[(size_t)(1*256+J0)*256+kh]; z1=Whh[(size_t)(1*256+J1)*256+kh];
                n0=Whh[(size_t)(2*256+J0)*256+kh]; n1=Whh[(size_t)(2*256+J1)*256+kh];
            }
            *(float2*)&wrz[(size_t)i*6+2*kk+0]=make_float2(r0,r1);
            *(float2*)&wrz[(size_t)i*6+2*kk+1]=make_float2(z0,z1);
            *(float2*)&wn2[(size_t)i*2+kk]=make_float2(n0,n1);
        }
    }
    const float* bi=bih1+bwd*768; const float* bh=bhh1+bwd*768;
    const float cr0=bi[j0]+bh[j0],       cr1=bi[j1]+bh[j1];
    const float cz0=bi[256+j0]+bh[256+j0], cz1=bi[256+j1]+bh[256+j1];
    const float cx0=bi[512+j0], cx1=bi[512+j1];
    const float cn0=bh[512+j0], cn1=bh[512+j1];

    unsigned ph=1;
    if(!bwd){
        if(jt==0){float4 z4={0,0,0,0};float4* d=(float4*)&g_hb1[0][bt*32*Hsz];
            for(int i=tid;i<32*Hsz/4;i+=256)d[i]=z4;}
        gbar(g_fl1,blockIdx.x,128,ph++);
    }
    const int tsteps=bwd?1:Tsz;

    for(int s=0;s<tsteps;s++){
        const int t=bwd?255:s;
        const float* hp=g_hb1[s&1];
        u64 ar=0,az=0,anx=0,anh=0;
        const float2* xp=(const float2*)&g_h1[((size_t)bg*Tsz+t)*512];
        #pragma unroll 8
        for(int k2=0;k2<256;k2++){
            float2 xv=__ldg(&xp[k2]);
            u64 x0=dup2(xv.x),x1=dup2(xv.y);
            const u64* sl=&wrz[(size_t)(k2*8+jp)*6];
            ulonglong2 rz0=*(const ulonglong2*)sl;
            ulonglong2 rz1=*(const ulonglong2*)(sl+2);
            ulonglong2 nn=*(const ulonglong2*)&wn2[(size_t)(k2*8+jp)*2];
            ar=ffma2(x0,rz0.x,ar); az=ffma2(x0,rz0.y,az); anx=ffma2(x0,nn.x,anx);
            ar=ffma2(x1,rz1.x,ar); az=ffma2(x1,rz1.y,az); anx=ffma2(x1,nn.y,anx);
        }
        float2 hpv=make_float2(0.f,0.f);
        if(!bwd){
            hpv=ldcg2((const float2*)&hp[bg*Hsz+j0]);
            const float2* hp2=(const float2*)&hp[bg*Hsz];
            #pragma unroll 8
            for(int k2=256;k2<384;k2++){
                float2 xv=ldcg2(&hp2[k2-256]);
                u64 x0=dup2(xv.x),x1=dup2(xv.y);
                const u64* sl=&wrz[(size_t)(k2*8+jp)*6];
                ulonglong2 rz0=*(const ulonglong2*)sl;
                ulonglong2 rz1=*(const ulonglong2*)(sl+2);
                ulonglong2 nn=*(const ulonglong2*)&wn2[(size_t)(k2*8+jp)*2];
                ar=ffma2(x0,rz0.x,ar); az=ffma2(x0,rz0.y,az); anh=ffma2(x0,nn.x,anh);
                ar=ffma2(x1,rz1.x,ar); az=ffma2(x1,rz1.y,az); anh=ffma2(x1,nn.y,anh);
            }
        }
        float r0=sigm(lo2(ar)+cr0), r1=sigm(hi2(ar)+cr1);
        float z0=sigm(lo2(az)+cz0), z1=sigm(hi2(az)+cz1);
        float n0=tanhf(lo2(anx)+cx0+r0*(lo2(anh)+cn0));
        float n1=tanhf(hi2(anx)+cx1+r1*(hi2(anh)+cn1));
        float h0=(1.f-z0)*n0+z0*hpv.x, h1=(1.f-z1)*n1+z1*hpv.y;
        float* outp=bwd?g_h2b:((t==255)?g_h2f:g_hb1[(s&1)^1]);
        *(float2*)&outp[bg*Hsz+j0]=make_float2(h0,h1);
        if(!bwd)gbar(g_fl1,blockIdx.x,128,ph++);
    }
    if(!bwd&&tid==0){unsigned o=atomicAdd(&g_ex1,1u);
        if(o==127u){for(int i=0;i<128;i++)((volatile unsigned*)g_fl1)[i]=0;g_ex1=0;__threadfence();}}
}

// ------------------------------ head --------------------------------------
__global__ void gru_head(const float* __restrict__ W_out,
                         const float* __restrict__ b_out,float* __restrict__ out){
    const int b=blockIdx.x, tid=threadIdx.x;   // 256 blocks x 128 threads
    float a0=0,a1=0,a2=0;
    for(int k=tid;k<Hsz;k+=128){
        float v=g_h2f[b*Hsz+k]+g_h2b[b*Hsz+k];
        a0+=v*W_out[k];a1+=v*W_out[256+k];a2+=v*W_out[512+k];
    }
    #pragma unroll
    for(int o=16;o>0;o>>=1){
        a0+=__shfl_xor_sync(0xffffffffu,a0,o);
        a1+=__shfl_xor_sync(0xffffffffu,a1,o);
        a2+=__shfl_xor_sync(0xffffffffu,a2,o);
    }
    __shared__ float red[3][4];
    if((tid&31)==0){int w=tid>>5;red[0][w]=a0;red[1][w]=a1;red[2][w]=a2;}
    __syncthreads();
    if(tid==0){
        a0=red[0][0]+red[0][1]+red[0][2]+red[0][3]+b_out[0];
        a1=red[1][0]+red[1][1]+red[1][2]+red[1][3]+b_out[1];
        a2=red[2][0]+red[2][1]+red[2][2]+red[2][3]+b_out[2];
        float m=fmaxf(a0,fmaxf(a1,a2));
        float e0=expf(a0-m),e1=expf(a1-m),e2=expf(a2-m);
        float inv=1.f/(e0+e1+e2);
        out[b*3+0]=e0*inv;out[b*3+1]=e1*inv;out[b*3+2]=e2*inv;
    }
}

extern "C" void kernel_launch(void* const* d_in,const int* in_sizes,int n_in,
                              void* d_out,int out_size){
    const float* x=(const float*)d_in[0];
    const float* Wih0=(const float*)d_in[1];
    const float* Whh0=(const float*)d_in[2];
    const float* bih0=(const float*)d_in[3];
    const float* bhh0=(const float*)d_in[4];
    const float* Wih1=(const float*)d_in[5];
    const float* Whh1=(const float*)d_in[6];
    const float* bih1=(const float*)d_in[7];
    const float* bhh1=(const float*)d_in[8];
    const float* W_out=(const float*)d_in[9];
    const float* b_out=(const float*)d_in[10];
    float* out=(float*)d_out;

    const int sm0=8192*8;        // 65,536 B
    const int sm1=24576*8;       // 196,608 B
    cudaFuncSetAttribute(gru0,cudaFuncAttributeMaxDynamicSharedMemorySize,sm0);
    cudaFuncSetAttribute(gru1,cudaFuncAttributeMaxDynamicSharedMemorySize,sm1);

    gru0<<<128,256,sm0>>>(x,Wih0,Whh0,bih0,bhh0);
    gru1<<<128,256,sm1>>>(Wih1,Whh1,bih1,bhh1,0);
    gru1<<<128,256,sm1>>>(Wih1,Whh1,bih1,bhh1,1);
    gru_head<<<256,128>>>(W_out,b_out,out);
}

// round 8
// speedup vs baseline: 1.0053x; 1.0053x over previous
#include <cuda_runtime.h>
#include <math.h>

#define Tsz 256
#define Hsz 256
#define FSTR 32   // flag stride: 32 u32 = 128B -> spreads across L2 slices

__device__ float g_h1[(size_t)256*256*512];
__device__ float g_hb0[2][2][256*256];
__device__ float g_hb1[2][256*256];
__device__ float g_h2f[256*256];
__device__ float g_h2b[256*256];
__device__ unsigned g_fl0[128*FSTR], g_fl1[128*FSTR], g_ex0, g_ex1;

typedef unsigned long long u64;
__device__ __forceinline__ u64 ffma2(u64 a,u64 b,u64 c){u64 d;asm("fma.rn.f32x2 %0,%1,%2,%3;":"=l"(d):"l"(a),"l"(b),"l"(c));return d;}
__device__ __forceinline__ u64 dup2(float v){u64 d;asm("mov.b64 %0,{%1,%2};":"=l"(d):"f"(v),"f"(v));return d;}
__device__ __forceinline__ float lo2(u64 v){return __uint_as_float((unsigned)v);}
__device__ __forceinline__ float hi2(u64 v){return __uint_as_float((unsigned)(v>>32));}
__device__ __forceinline__ float sigm(float v){return 1.f/(1.f+__expf(-v));}
__device__ __forceinline__ float2 ldcg2(const float2* p){float2 v;
    asm volatile("ld.global.cg.v2.f32 {%0,%1},[%2];":"=f"(v.x),"=f"(v.y):"l"(p));return v;}

__device__ __forceinline__ void gbar(unsigned* fl,int lbid,int nb,unsigned tgt){
    __syncthreads();
    if(threadIdx.x==0){__threadfence();atomicExch(&fl[lbid*FSTR],tgt);}
    int tid=threadIdx.x;
    for(;;){
        int ok=1;
        if(tid<nb){unsigned v;asm volatile("ld.global.cg.u32 %0,[%1];":"=r"(v):"l"(fl+(size_t)tid*FSTR));ok=(v>=tgt);}
        if(__syncthreads_and(ok))break;
    }
}

// ===== layer 0: 128 blocks = dir(2) x bt(4 of 64b) x jt(16 of 16j) ========
__global__ void __launch_bounds__(256,1) gru0(
    const float* __restrict__ x,const float* __restrict__ Wih0,
    const float* __restrict__ Whh0,const float* __restrict__ bih0,
    const float* __restrict__ bhh0)
{
    extern __shared__ __align__(16) u64 smu[];
    u64* wrz=smu;            // 1024 slots x 6 u64 (48B): (r0,z0 | r1,z1 | pad)
    u64* wn2=smu+6144;       // 1024 slots x 2 u64: (n0, n1)
    const int dir=blockIdx.x>>6, lb=blockIdx.x&63;
    const int bt=lb>>4, jt=lb&15, tid=threadIdx.x;
    const int tb=tid>>3, jp=tid&7;
    const int b0=bt*64+tb*2, b1=b0+1;
    const int j0=jt*16+2*jp, j1=j0+1;

    const float* Whh=Whh0+(size_t)dir*768*Hsz;
    for(int i=tid;i<1024;i+=256){
        int k2=i>>3, p=i&7, k0=2*k2;
        int J0=jt*16+2*p, J1=J0+1;
        #pragma unroll
        for(int kk=0;kk<2;kk++){
            float r0=Whh[(size_t)(0*256+J0)*256+k0+kk], r1=Whh[(size_t)(0*256+J1)*256+k0+kk];
            float z0=Whh[(size_t)(1*256+J0)*256+k0+kk], z1=Whh[(size_t)(1*256+J1)*256+k0+kk];
            float n0=Whh[(size_t)(2*256+J0)*256+k0+kk], n1=Whh[(size_t)(2*256+J1)*256+k0+kk];
            *(float2*)&wrz[(size_t)i*6+2*kk+0]=make_float2(r0,r1);
            *(float2*)&wrz[(size_t)i*6+2*kk+1]=make_float2(z0,z1);
            *(float2*)&wn2[(size_t)i*2+kk]=make_float2(n0,n1);
        }
    }
    const float* Wih=Wih0+(size_t)dir*768*4;
    const float4 wxr0=*(const float4*)&Wih[(0*256+j0)*4], wxr1=*(const float4*)&Wih[(0*256+j1)*4];
    const float4 wxz0=*(const float4*)&Wih[(1*256+j0)*4], wxz1=*(const float4*)&Wih[(1*256+j1)*4];
    const float4 wxn0=*(const float4*)&Wih[(2*256+j0)*4], wxn1=*(const float4*)&Wih[(2*256+j1)*4];
    const float* bi=bih0+dir*768; const float* bh=bhh0+dir*768;
    const float cr0=bi[j0],cr1=bi[j1],cz0=bi[256+j0],cz1=bi[256+j1],cn0=bi[512+j0],cn1=bi[512+j1];
    const float br0=bh[j0],br1=bh[j1],bz0=bh[256+j0],bz1=bh[256+j1],bn0=bh[512+j0],bn1=bh[512+j1];

    if(jt==0){float4 z4={0,0,0,0};float4* d=(float4*)&g_hb0[dir][0][bt*64*Hsz];
        for(int i=tid;i<64*Hsz/4;i+=256)d[i]=z4;}
    unsigned ph=1;
    gbar(g_fl0+(size_t)dir*64*FSTR,lb,64,ph++);

    for(int s=0;s<Tsz;s++){
        const int t=dir?255-s:s;
        const float* hp=g_hb0[dir][s&1];
        float* hn_=g_hb0[dir][(s&1)^1];
        const float2* xpa=(const float2*)&hp[b0*Hsz];
        const float2* xpb=(const float2*)&hp[b1*Hsz];
        float2 hpa=ldcg2((const float2*)&hp[b0*Hsz+j0]);
        float2 hpb=ldcg2((const float2*)&hp[b1*Hsz+j0]);
        float4 xva=((const float4*)x)[(size_t)b0*Tsz+t];
        float4 xvb=((const float4*)x)[(size_t)b1*Tsz+t];

        u64 arA=0,azA=0,anA=0,arB=0,azB=0,anB=0;
        #pragma unroll 8
        for(int k2=0;k2<128;k2++){
            float2 ha=ldcg2(&xpa[k2]), hb=ldcg2(&xpb[k2]);
            u64 a0=dup2(ha.x),a1=dup2(ha.y),c0=dup2(hb.x),c1=dup2(hb.y);
            const u64* sl=&wrz[(size_t)(k2*8+jp)*6];
            ulonglong2 rz0=*(const ulonglong2*)sl;
            ulonglong2 rz1=*(const ulonglong2*)(sl+2);
            ulonglong2 nn=*(const ulonglong2*)&wn2[(size_t)(k2*8+jp)*2];
            arA=ffma2(a0,rz0.x,arA); azA=ffma2(a0,rz0.y,azA); anA=ffma2(a0,nn.x,anA);
            arA=ffma2(a1,rz1.x,arA); azA=ffma2(a1,rz1.y,azA); anA=ffma2(a1,nn.y,anA);
            arB=ffma2(c0,rz0.x,arB); azB=ffma2(c0,rz0.y,azB); anB=ffma2(c0,nn.x,anB);
            arB=ffma2(c1,rz1.x,arB); azB=ffma2(c1,rz1.y,azB); anB=ffma2(c1,nn.y,anB);
        }
        #pragma unroll
        for(int bb=0;bb<2;bb++){
            float4 xv=bb?xvb:xva; float2 hpv=bb?hpb:hpa;
            u64 ar=bb?arB:arA, az=bb?azB:azA, an=bb?anB:anA;
            int bg=bb?b1:b0;
            float xr0=cr0+xv.x*wxr0.x+xv.y*wxr0.y+xv.z*wxr0.z+xv.w*wxr0.w;
            float xr1=cr1+xv.x*wxr1.x+xv.y*wxr1.y+xv.z*wxr1.z+xv.w*wxr1.w;
            float xz0=cz0+xv.x*wxz0.x+xv.y*wxz0.y+xv.z*wxz0.z+xv.w*wxz0.w;
            float xz1=cz1+xv.x*wxz1.x+xv.y*wxz1.y+xv.z*wxz1.z+xv.w*wxz1.w;
            float xn0=cn0+xv.x*wxn0.x+xv.y*wxn0.y+xv.z*wxn0.z+xv.w*wxn0.w;
            float xn1=cn1+xv.x*wxn1.x+xv.y*wxn1.y+xv.z*wxn1.z+xv.w*wxn1.w;
            float r0=sigm(xr0+lo2(ar)+br0), r1=sigm(xr1+hi2(ar)+br1);
            float z0=sigm(xz0+lo2(az)+bz0), z1=sigm(xz1+hi2(az)+bz1);
            float n0=tanhf(xn0+r0*(lo2(an)+bn0)), n1=tanhf(xn1+r1*(hi2(an)+bn1));
            float h0=(1.f-z0)*n0+z0*hpv.x, h1=(1.f-z1)*n1+z1*hpv.y;
            *(float2*)&hn_[bg*Hsz+j0]=make_float2(h0,h1);
            *(float2*)&g_h1[((size_t)bg*Tsz+t)*512+dir*Hsz+j0]=make_float2(h0,h1);
        }
        gbar(g_fl0+(size_t)dir*64*FSTR,lb,64,ph++);
    }
    if(tid==0){unsigned o=atomicAdd(&g_ex0,1u);
        if(o==127u){for(int i=0;i<128;i++)((volatile unsigned*)g_fl0)[i*FSTR]=0;g_ex0=0;__threadfence();}}
}

// ===== layer 1: 256 blocks. 0-127: fwd persistent (barrier group).
//                128-255: single bwd step (t=255, h=0), no barrier, exit. ====
__global__ void __launch_bounds__(256,1) gru1(
    const float* __restrict__ Wih1,const float* __restrict__ Whh1,
    const float* __restrict__ bih1,const float* __restrict__ bhh1)
{
    extern __shared__ __align__(16) u64 smu[];
    u64* wrz=smu;            // 3072 slots x 6 u64 (48B)
    u64* wn2=smu+18432;      // 3072 slots x 2 u64
    const int bwd=(blockIdx.x>=128)?1:0;
    const int lb=blockIdx.x&127;
    const int bt=lb>>4, jt=lb&15, tid=threadIdx.x;
    const int b=tid>>3, jp=tid&7;
    const int bg=bt*32+b;
    const int j0=jt*16+2*jp, j1=j0+1;
    const float* Wih=Wih1+(size_t)bwd*768*512;
    const float* Whh=Whh1+(size_t)bwd*768*Hsz;

    for(int i=tid;i<3072;i+=256){
        int k2=i>>3, p=i&7, k0=2*k2;
        int J0=jt*16+2*p, J1=J0+1;
        #pragma unroll
        for(int kk=0;kk<2;kk++){
            int k=k0+kk;
            float r0,r1,z0,z1,n0,n1;
            if(k<512){
                r0=Wih[(size_t)(0*256+J0)*512+k]; r1=Wih[(size_t)(0*256+J1)*512+k];
                z0=Wih[(size_t)(1*256+J0)*512+k]; z1=Wih[(size_t)(1*256+J1)*512+k];
                n0=Wih[(size_t)(2*256+J0)*512+k]; n1=Wih[(size_t)(2*256+J1)*512+k];
            }else{
                int kh=k-512;
                r0=Whh[(size_t)(0*256+J0)*256+kh]; r1=Whh[(size_t)(0*256+J1)*256+kh];
                z0=Whh[(size_t)(1*256+J0)*256+kh]; z1=Whh[(size_t)(1*256+J1)*256+kh];
                n0=Whh[(size_t)(2*256+J0)*256+kh]; n1=Whh[(size_t)(2*256+J1)*256+kh];
            }
            *(float2*)&wrz[(size_t)i*6+2*kk+0]=make_float2(r0,r1);
            *(float2*)&wrz[(size_t)i*6+2*kk+1]=make_float2(z0,z1);
            *(float2*)&wn2[(size_t)i*2+kk]=make_float2(n0,n1);
        }
    }
    const float* bi=bih1+bwd*768; const float* bh=bhh1+bwd*768;
    const float cr0=bi[j0]+bh[j0],       cr1=bi[j1]+bh[j1];
    const float cz0=bi[256+j0]+bh[256+j0], cz1=bi[256+j1]+bh[256+j1];
    const float cx0=bi[512+j0], cx1=bi[512+j1];
    const float cn0=bh[512+j0], cn1=bh[512+j1];

    unsigned ph=1;
    if(!bwd){
        if(jt==0){float4 z4={0,0,0,0};float4* d=(float4*)&g_hb1[0][bt*32*Hsz];
            for(int i=tid;i<32*Hsz/4;i+=256)d[i]=z4;}
        gbar(g_fl1,lb,128,ph++);
    }
    const int tsteps=bwd?1:Tsz;

    for(int s=0;s<tsteps;s++){
        const int t=bwd?255:s;
        const float* hp=g_hb1[s&1];
        u64 ar=0,az=0,anx=0,anh=0;
        const float2* xp=(const float2*)&g_h1[((size_t)bg*Tsz+t)*512];
        #pragma unroll 8
        for(int k2=0;k2<256;k2++){
            float2 xv=__ldg(&xp[k2]);
            u64 x0=dup2(xv.x),x1=dup2(xv.y);
            const u64* sl=&wrz[(size_t)(k2*8+jp)*6];
            ulonglong2 rz0=*(const ulonglong2*)sl;
            ulonglong2 rz1=*(const ulonglong2*)(sl+2);
            ulonglong2 nn=*(const ulonglong2*)&wn2[(size_t)(k2*8+jp)*2];
            ar=ffma2(x0,rz0.x,ar); az=ffma2(x0,rz0.y,az); anx=ffma2(x0,nn.x,anx);
            ar=ffma2(x1,rz1.x,ar); az=ffma2(x1,rz1.y,az); anx=ffma2(x1,nn.y,anx);
        }
        float2 hpv=make_float2(0.f,0.f);
        if(!bwd){
            hpv=ldcg2((const float2*)&hp[bg*Hsz+j0]);
            const float2* hp2=(const float2*)&hp[bg*Hsz];
            #pragma unroll 8
            for(int k2=256;k2<384;k2++){
                float2 xv=ldcg2(&hp2[k2-256]);
                u64 x0=dup2(xv.x),x1=dup2(xv.y);
                const u64* sl=&wrz[(size_t)(k2*8+jp)*6];
                ulonglong2 rz0=*(const ulonglong2*)sl;
                ulonglong2 rz1=*(const ulonglong2*)(sl+2);
                ulonglong2 nn=*(const ulonglong2*)&wn2[(size_t)(k2*8+jp)*2];
                ar=ffma2(x0,rz0.x,ar); az=ffma2(x0,rz0.y,az); anh=ffma2(x0,nn.x,anh);
                ar=ffma2(x1,rz1.x,ar); az=ffma2(x1,rz1.y,az); anh=ffma2(x1,nn.y,anh);
            }
        }
        float r0=sigm(lo2(ar)+cr0), r1=sigm(hi2(ar)+cr1);
        float z0=sigm(lo2(az)+cz0), z1=sigm(hi2(az)+cz1);
        float n0=tanhf(lo2(anx)+cx0+r0*(lo2(anh)+cn0));
        float n1=tanhf(hi2(anx)+cx1+r1*(hi2(anh)+cn1));
        float h0=(1.f-z0)*n0+z0*hpv.x, h1=(1.f-z1)*n1+z1*hpv.y;
        float* outp=bwd?g_h2b:((t==255)?g_h2f:g_hb1[(s&1)^1]);
        *(float2*)&outp[bg*Hsz+j0]=make_float2(h0,h1);
        if(!bwd)gbar(g_fl1,lb,128,ph++);
    }
    if(!bwd&&tid==0){unsigned o=atomicAdd(&g_ex1,1u);
        if(o==127u){for(int i=0;i<128;i++)((volatile unsigned*)g_fl1)[i*FSTR]=0;g_ex1=0;__threadfence();}}
}

// ------------------------------ head --------------------------------------
__global__ void gru_head(const float* __restrict__ W_out,
                         const float* __restrict__ b_out,float* __restrict__ out){
    const int b=blockIdx.x, tid=threadIdx.x;   // 256 blocks x 128 threads
    float a0=0,a1=0,a2=0;
    for(int k=tid;k<Hsz;k+=128){
        float v=g_h2f[b*Hsz+k]+g_h2b[b*Hsz+k];
        a0+=v*W_out[k];a1+=v*W_out[256+k];a2+=v*W_out[512+k];
    }
    #pragma unroll
    for(int o=16;o>0;o>>=1){
        a0+=__shfl_xor_sync(0xffffffffu,a0,o);
        a1+=__shfl_xor_sync(0xffffffffu,a1,o);
        a2+=__shfl_xor_sync(0xffffffffu,a2,o);
    }
    __shared__ float red[3][4];
    if((tid&31)==0){int w=tid>>5;red[0][w]=a0;red[1][w]=a1;red[2][w]=a2;}
    __syncthreads();
    if(tid==0){
        a0=red[0][0]+red[0][1]+red[0][2]+red[0][3]+b_out[0];
        a1=red[1][0]+red[1][1]+red[1][2]+red[1][3]+b_out[1];
        a2=red[2][0]+red[2][1]+red[2][2]+red[2][3]+b_out[2];
        float m=fmaxf(a0,fmaxf(a1,a2));
        float e0=expf(a0-m),e1=expf(a1-m),e2=expf(a2-m);
        float inv=1.f/(e0+e1+e2);
        out[b*3+0]=e0*inv;out[b*3+1]=e1*inv;out[b*3+2]=e2*inv;
    }
}

extern "C" void kernel_launch(void* const* d_in,const int* in_sizes,int n_in,
                              void* d_out,int out_size){
    const float* x=(const float*)d_in[0];
    const float* Wih0=(const float*)d_in[1];
    const float* Whh0=(const float*)d_in[2];
    const float* bih0=(const float*)d_in[3];
    const float* bhh0=(const float*)d_in[4];
    const float* Wih1=(const float*)d_in[5];
    const float* Whh1=(const float*)d_in[6];
    const float* bih1=(const float*)d_in[7];
    const float* bhh1=(const float*)d_in[8];
    const float* W_out=(const float*)d_in[9];
    const float* b_out=(const float*)d_in[10];
    float* out=(float*)d_out;

    const int sm0=8192*8;        // 65,536 B
    const int sm1=24576*8;       // 196,608 B
    cudaFuncSetAttribute(gru0,cudaFuncAttributeMaxDynamicSharedMemorySize,sm0);
    cudaFuncSetAttribute(gru1,cudaFuncAttributeMaxDynamicSharedMemorySize,sm1);

    gru0<<<128,256,sm0>>>(x,Wih0,Whh0,bih0,bhh0);
    gru1<<<256,256,sm1>>>(Wih1,Whh1,bih1,bhh1);
    gru_head<<<256,128>>>(W_out,b_out,out);
}

// round 9
// speedup vs baseline: 1.5487x; 1.5405x over previous
#include <cuda_runtime.h>
#include <math.h>

#define Tsz 256
#define Hsz 256

__device__ float g_h1[(size_t)256*256*512];     // layer-0 output [b][t][512]
__device__ float g_xp[(size_t)65536*768];       // layer-1 x-projection [b*256+t][768]
__device__ float g_h2f[256*256];
__device__ float g_h2b[256*256];

typedef unsigned long long u64;
__device__ __forceinline__ u64 ffma2(u64 a,u64 b,u64 c){u64 d;asm("fma.rn.f32x2 %0,%1,%2,%3;":"=l"(d):"l"(a),"l"(b),"l"(c));return d;}
__device__ __forceinline__ u64 dup2(float v){u64 d;asm("mov.b64 %0,{%1,%2};":"=l"(d):"f"(v),"f"(v));return d;}
__device__ __forceinline__ u64 pk2(float a,float b){u64 d;asm("mov.b64 %0,{%1,%2};":"=l"(d):"f"(a),"f"(b));return d;}
__device__ __forceinline__ float lo2(u64 v){return __uint_as_float((unsigned)v);}
__device__ __forceinline__ float hi2(u64 v){return __uint_as_float((unsigned)(v>>32));}
__device__ __forceinline__ float f2sum(u64 v){return lo2(v)+hi2(v);}
__device__ __forceinline__ float sigm(float v){return 1.f/(1.f+__expf(-v));}

__device__ __forceinline__ unsigned smaddr(const void* p){unsigned a;
    asm("{.reg .u64 t; cvta.to.shared.u64 t,%1; cvt.u32.u64 %0,t;}":"=r"(a):"l"(p));return a;}
__device__ __forceinline__ unsigned mapar(unsigned a,unsigned r){unsigned o;
    asm("mapa.shared::cluster.u32 %0,%1,%2;":"=r"(o):"r"(a),"r"(r));return o;}
__device__ __forceinline__ void stc(unsigned a,float v){
    asm volatile("st.shared::cluster.b32 [%0],%1;"::"r"(a),"f"(v):"memory");}
#define CSYNC() do{asm volatile("barrier.cluster.arrive.aligned;":::"memory"); \
                   asm volatile("barrier.cluster.wait.aligned;":::"memory");}while(0)

// ===== layer 0: 32 clusters x 4 CTAs. Cluster = 16 seqs of one dir.
// CTA rank q holds Whh j-quarter [64q,64q+64). Thread: 2 seqs x j-pair.
__global__ void __launch_bounds__(256,1) __cluster_dims__(4,1,1) gru0(
    const float* __restrict__ x,const float* __restrict__ Wih0,
    const float* __restrict__ Whh0,const float* __restrict__ bih0,
    const float* __restrict__ bhh0)
{
    extern __shared__ __align__(16) unsigned char smraw[];
    u64* wsl=(u64*)smraw;                    // [256k][32jp][3] u64 = 192KB
    float* hs=(float*)(smraw+196608);        // [256 hid][16 seq] = 16KB
    unsigned q; asm("mov.u32 %0,%%cluster_ctarank;":"=r"(q));
    const int cid=blockIdx.x>>2;
    const int dir=cid>>4, bbase=(cid&15)*16;
    const int tid=threadIdx.x, w=tid>>5, lane=tid&31;
    const int jp=(lane&7)|((w&3)<<3);        // 0..31
    const int sg=(lane>>3)|((w>>2)<<2);      // 0..7 (2 seqs each)
    const int j0=q*64+2*jp, j1=j0+1;

    const float* Whh=Whh0+(size_t)dir*768*256;
    for(int i=tid;i<256*32;i+=256){          // i = k*32 + p
        int k=i>>5,p=i&31,jj=q*64+2*p;
        u64* sl=&wsl[(size_t)i*3];
        sl[0]=pk2(Whh[(size_t)(0*256+jj)*256+k],Whh[(size_t)(0*256+jj+1)*256+k]);
        sl[1]=pk2(Whh[(size_t)(1*256+jj)*256+k],Whh[(size_t)(1*256+jj+1)*256+k]);
        sl[2]=pk2(Whh[(size_t)(2*256+jj)*256+k],Whh[(size_t)(2*256+jj+1)*256+k]);
    }
    const float* Wih=Wih0+(size_t)dir*768*4;
    const float4 wxr0=*(const float4*)&Wih[(0*256+j0)*4], wxr1=*(const float4*)&Wih[(0*256+j1)*4];
    const float4 wxz0=*(const float4*)&Wih[(1*256+j0)*4], wxz1=*(const float4*)&Wih[(1*256+j1)*4];
    const float4 wxn0=*(const float4*)&Wih[(2*256+j0)*4], wxn1=*(const float4*)&Wih[(2*256+j1)*4];
    const float* bi=bih0+dir*768; const float* bh=bhh0+dir*768;
    const float cr0=bi[j0],cr1=bi[j1],cz0=bi[256+j0],cz1=bi[256+j1],cn0=bi[512+j0],cn1=bi[512+j1];
    const float br0=bh[j0],br1=bh[j1],bz0=bh[256+j0],bz1=bh[256+j1],bn0=bh[512+j0],bn1=bh[512+j1];

    for(int i=tid;i<4096;i+=256)hs[i]=0.f;
    unsigned hsa=smaddr(hs);
    unsigned peer[4];
    #pragma unroll
    for(int r=0;r<4;r++)peer[r]=mapar(hsa,r);
    __syncthreads();

    const int s0=2*sg, s1=s0+1;
    const int bg0=bbase+s0, bg1=bbase+s1;
    const u64* hk=(const u64*)hs;

    for(int s=0;s<Tsz;s++){
        const int t=dir?255-s:s;
        u64 aR0=0,aZ0=0,aN0=0,aR1=0,aZ1=0,aN1=0;
        #pragma unroll 8
        for(int k=0;k<256;k++){
            u64 h2=hk[k*8+sg];
            u64 hA=dup2(lo2(h2)),hB=dup2(hi2(h2));
            const u64* sl=&wsl[(size_t)(k*32+jp)*3];
            u64 wr=sl[0],wz=sl[1],wn=sl[2];
            aR0=ffma2(hA,wr,aR0); aZ0=ffma2(hA,wz,aZ0); aN0=ffma2(hA,wn,aN0);
            aR1=ffma2(hB,wr,aR1); aZ1=ffma2(hB,wz,aZ1); aN1=ffma2(hB,wn,aN1);
        }
        float4 xv0=((const float4*)x)[(size_t)bg0*256+t];
        float4 xv1=((const float4*)x)[(size_t)bg1*256+t];
        float hp00=hs[j0*16+s0],hp01=hs[j1*16+s0];
        float hp10=hs[j0*16+s1],hp11=hs[j1*16+s1];

        float xr0=cr0+xv0.x*wxr0.x+xv0.y*wxr0.y+xv0.z*wxr0.z+xv0.w*wxr0.w;
        float xr1=cr1+xv0.x*wxr1.x+xv0.y*wxr1.y+xv0.z*wxr1.z+xv0.w*wxr1.w;
        float xz0=cz0+xv0.x*wxz0.x+xv0.y*wxz0.y+xv0.z*wxz0.z+xv0.w*wxz0.w;
        float xz1=cz1+xv0.x*wxz1.x+xv0.y*wxz1.y+xv0.z*wxz1.z+xv0.w*wxz1.w;
        float xn0=cn0+xv0.x*wxn0.x+xv0.y*wxn0.y+xv0.z*wxn0.z+xv0.w*wxn0.w;
        float xn1=cn1+xv0.x*wxn1.x+xv0.y*wxn1.y+xv0.z*wxn1.z+xv0.w*wxn1.w;
        float r0=sigm(xr0+lo2(aR0)+br0), r1=sigm(xr1+hi2(aR0)+br1);
        float z0=sigm(xz0+lo2(aZ0)+bz0), z1=sigm(xz1+hi2(aZ0)+bz1);
        float n0=tanhf(xn0+r0*(lo2(aN0)+bn0)), n1=tanhf(xn1+r1*(hi2(aN0)+bn1));
        float hA0=(1.f-z0)*n0+z0*hp00, hA1=(1.f-z1)*n1+z1*hp01;

        xr0=cr0+xv1.x*wxr0.x+xv1.y*wxr0.y+xv1.z*wxr0.z+xv1.w*wxr0.w;
        xr1=cr1+xv1.x*wxr1.x+xv1.y*wxr1.y+xv1.z*wxr1.z+xv1.w*wxr1.w;
        xz0=cz0+xv1.x*wxz0.x+xv1.y*wxz0.y+xv1.z*wxz0.z+xv1.w*wxz0.w;
        xz1=cz1+xv1.x*wxz1.x+xv1.y*wxz1.y+xv1.z*wxz1.z+xv1.w*wxz1.w;
        xn0=cn0+xv1.x*wxn0.x+xv1.y*wxn0.y+xv1.z*wxn0.z+xv1.w*wxn0.w;
        xn1=cn1+xv1.x*wxn1.x+xv1.y*wxn1.y+xv1.z*wxn1.z+xv1.w*wxn1.w;
        r0=sigm(xr0+lo2(aR1)+br0); r1=sigm(xr1+hi2(aR1)+br1);
        z0=sigm(xz0+lo2(aZ1)+bz0); z1=sigm(xz1+hi2(aZ1)+bz1);
        n0=tanhf(xn0+r0*(lo2(aN1)+bn0)); n1=tanhf(xn1+r1*(hi2(aN1)+bn1));
        float hB0=(1.f-z0)*n0+z0*hp10, hB1=(1.f-z1)*n1+z1*hp11;

        CSYNC();   // all CTAs done reading h_prev
        #pragma unroll
        for(int r=0;r<4;r++){
            unsigned pb=peer[r];
            stc(pb+(unsigned)(j0*16+s0)*4,hA0); stc(pb+(unsigned)(j1*16+s0)*4,hA1);
            stc(pb+(unsigned)(j0*16+s1)*4,hB0); stc(pb+(unsigned)(j1*16+s1)*4,hB1);
        }
        *(float2*)&g_h1[((size_t)bg0*256+t)*512+dir*256+j0]=make_float2(hA0,hA1);
        *(float2*)&g_h1[((size_t)bg1*256+t)*512+dir*256+j0]=make_float2(hB0,hB1);
        CSYNC();   // new h visible everywhere
    }
}

// ===== xp GEMM: g_xp[m][n] = g_h1[m][k] * Wih1[0][n][k], m=65536,n=768,k=512
__global__ void __launch_bounds__(256,2) xpg(const float* __restrict__ W){
    __shared__ float As[2][16][68], Bs[2][16][68];
    const int bn=blockIdx.x, bm=blockIdx.y;
    const int tid=threadIdx.x, tx=tid&15, ty=tid>>4;
    const int r=tid>>2, s=tid&3;
    const float* Ar=g_h1+(size_t)(bm*64+r)*512+4*s;
    const float* Br=W+(size_t)(bn*64+r)*512+4*s;
    u64 acc[4][2]={};
    float4 a=*(const float4*)Ar, b=*(const float4*)Br;
    As[0][4*s+0][r]=a.x;As[0][4*s+1][r]=a.y;As[0][4*s+2][r]=a.z;As[0][4*s+3][r]=a.w;
    Bs[0][4*s+0][r]=b.x;Bs[0][4*s+1][r]=b.y;Bs[0][4*s+2][r]=b.z;Bs[0][4*s+3][r]=b.w;
    __syncthreads();
    for(int kt=0;kt<32;kt++){
        const int buf=kt&1;
        if(kt<31){a=*(const float4*)(Ar+(kt+1)*16);b=*(const float4*)(Br+(kt+1)*16);}
        #pragma unroll
        for(int k=0;k<16;k++){
            float4 av=*(const float4*)&As[buf][k][4*ty];
            ulonglong2 bv=*(const ulonglong2*)&Bs[buf][k][4*tx];
            u64 a0=dup2(av.x),a1=dup2(av.y),a2=dup2(av.z),a3=dup2(av.w);
            acc[0][0]=ffma2(a0,bv.x,acc[0][0]); acc[0][1]=ffma2(a0,bv.y,acc[0][1]);
            acc[1][0]=ffma2(a1,bv.x,acc[1][0]); acc[1][1]=ffma2(a1,bv.y,acc[1][1]);
            acc[2][0]=ffma2(a2,bv.x,acc[2][0]); acc[2][1]=ffma2(a2,bv.y,acc[2][1]);
            acc[3][0]=ffma2(a3,bv.x,acc[3][0]); acc[3][1]=ffma2(a3,bv.y,acc[3][1]);
        }
        if(kt<31){
            const int nb=1-buf;
            As[nb][4*s+0][r]=a.x;As[nb][4*s+1][r]=a.y;As[nb][4*s+2][r]=a.z;As[nb][4*s+3][r]=a.w;
            Bs[nb][4*s+0][r]=b.x;Bs[nb][4*s+1][r]=b.y;Bs[nb][4*s+2][r]=b.z;Bs[nb][4*s+3][r]=b.w;
        }
        __syncthreads();
    }
    float* o=g_xp+(size_t)(bm*64+ty*4)*768+bn*64+tx*4;
    #pragma unroll
    for(int m=0;m<4;m++){
        *(float2*)(o+(size_t)m*768)  =make_float2(lo2(acc[m][0]),hi2(acc[m][0]));
        *(float2*)(o+(size_t)m*768+2)=make_float2(lo2(acc[m][1]),hi2(acc[m][1]));
    }
}

// ===== layer 1 fwd scan: 32 clusters x 4 CTAs, 8 seqs/cluster, K=256 only.
__global__ void __launch_bounds__(256,1) __cluster_dims__(4,1,1) gru1(
    const float* __restrict__ Whh1,const float* __restrict__ bih1,
    const float* __restrict__ bhh1)
{
    extern __shared__ __align__(16) unsigned char smraw[];
    u64* wsl=(u64*)smraw;                    // [256k][32jp][3]
    float* hs=(float*)(smraw+196608);        // [256 hid][8 seq] = 8KB
    unsigned q; asm("mov.u32 %0,%%cluster_ctarank;":"=r"(q));
    const int cid=blockIdx.x>>2;
    const int tid=threadIdx.x, w=tid>>5, lane=tid&31;
    const int jp=(lane&7)|((w&3)<<3);
    const int sq=(lane>>3)|((w>>2)<<2);      // 0..7, one seq each
    const int j0=q*64+2*jp, j1=j0+1;
    const int b=cid*8+sq;

    for(int i=tid;i<256*32;i+=256){
        int k=i>>5,p=i&31,jj=q*64+2*p;
        u64* sl=&wsl[(size_t)i*3];
        sl[0]=pk2(Whh1[(size_t)(0*256+jj)*256+k],Whh1[(size_t)(0*256+jj+1)*256+k]);
        sl[1]=pk2(Whh1[(size_t)(1*256+jj)*256+k],Whh1[(size_t)(1*256+jj+1)*256+k]);
        sl[2]=pk2(Whh1[(size_t)(2*256+jj)*256+k],Whh1[(size_t)(2*256+jj+1)*256+k]);
    }
    const float cr0=bih1[j0]+bhh1[j0],         cr1=bih1[j1]+bhh1[j1];
    const float cz0=bih1[256+j0]+bhh1[256+j0], cz1=bih1[256+j1]+bhh1[256+j1];
    const float cx0=bih1[512+j0], cx1=bih1[512+j1];
    const float cn0=bhh1[512+j0], cn1=bhh1[512+j1];

    for(int i=tid;i<2048;i+=256)hs[i]=0.f;
    unsigned hsa=smaddr(hs);
    unsigned peer[4];
    #pragma unroll
    for(int r=0;r<4;r++)peer[r]=mapar(hsa,r);
    __syncthreads();

    for(int t=0;t<Tsz;t++){
        u64 aR=0,aZ=0,aN=0;
        #pragma unroll 8
        for(int k=0;k<256;k++){
            u64 hv=dup2(hs[k*8+sq]);
            const u64* sl=&wsl[(size_t)(k*32+jp)*3];
            aR=ffma2(hv,sl[0],aR); aZ=ffma2(hv,sl[1],aZ); aN=ffma2(hv,sl[2],aN);
        }
        const float* xr_=&g_xp[(size_t)(b*256+t)*768];
        float2 pr=__ldg((const float2*)(xr_+j0));
        float2 pz=__ldg((const float2*)(xr_+256+j0));
        float2 pn=__ldg((const float2*)(xr_+512+j0));
        float hp0=hs[j0*8+sq], hp1=hs[j1*8+sq];
        float r0=sigm(pr.x+lo2(aR)+cr0), r1=sigm(pr.y+hi2(aR)+cr1);
        float z0=sigm(pz.x+lo2(aZ)+cz0), z1=sigm(pz.y+hi2(aZ)+cz1);
        float n0=tanhf(pn.x+cx0+r0*(lo2(aN)+cn0));
        float n1=tanhf(pn.y+cx1+r1*(hi2(aN)+cn1));
        float h0=(1.f-z0)*n0+z0*hp0, h1=(1.f-z1)*n1+z1*hp1;

        CSYNC();
        #pragma unroll
        for(int r=0;r<4;r++){
            unsigned pb=peer[r];
            stc(pb+(unsigned)(j0*8+sq)*4,h0); stc(pb+(unsigned)(j1*8+sq)*4,h1);
        }
        if(t==255)*(float2*)&g_h2f[b*256+j0]=make_float2(h0,h1);
        CSYNC();
    }
}

// ===== layer 1 single bwd step (h=0): pure x-projection with Wih1[1].
__global__ void __launch_bounds__(256,1) g1bwd(
    const float* __restrict__ Wih1,const float* __restrict__ bih1,
    const float* __restrict__ bhh1)
{
    const int bt=blockIdx.x>>4, jt=blockIdx.x&15;
    const int tid=threadIdx.x, bl=tid>>3, jp=tid&7;
    const int b=bt*32+bl, j0=jt*16+2*jp, j1=j0+1;
    const float* W=Wih1+(size_t)768*512;
    const float2* xp=(const float2*)&g_h1[((size_t)b*256+255)*512];
    const float2* wr0=(const float2*)&W[(size_t)(0*256+j0)*512];
    const float2* wr1=(const float2*)&W[(size_t)(0*256+j1)*512];
    const float2* wz0=(const float2*)&W[(size_t)(1*256+j0)*512];
    const float2* wz1=(const float2*)&W[(size_t)(1*256+j1)*512];
    const float2* wn0=(const float2*)&W[(size_t)(2*256+j0)*512];
    const float2* wn1=(const float2*)&W[(size_t)(2*256+j1)*512];
    u64 ar0=0,ar1=0,az0=0,az1=0,an0=0,an1=0;
    #pragma unroll 8
    for(int k2=0;k2<256;k2++){
        float2 xv=__ldg(&xp[k2]); u64 xu=pk2(xv.x,xv.y);
        float2 t0=__ldg(&wr0[k2]); ar0=ffma2(xu,pk2(t0.x,t0.y),ar0);
        float2 t1=__ldg(&wr1[k2]); ar1=ffma2(xu,pk2(t1.x,t1.y),ar1);
        float2 t2=__ldg(&wz0[k2]); az0=ffma2(xu,pk2(t2.x,t2.y),az0);
        float2 t3=__ldg(&wz1[k2]); az1=ffma2(xu,pk2(t3.x,t3.y),az1);
        float2 t4=__ldg(&wn0[k2]); an0=ffma2(xu,pk2(t4.x,t4.y),an0);
        float2 t5=__ldg(&wn1[k2]); an1=ffma2(xu,pk2(t5.x,t5.y),an1);
    }
    const float* bi=bih1+768; const float* bh=bhh1+768;
    float r0=sigm(f2sum(ar0)+bi[j0]+bh[j0]);
    float r1=sigm(f2sum(ar1)+bi[j1]+bh[j1]);
    float z0=sigm(f2sum(az0)+bi[256+j0]+bh[256+j0]);
    float z1=sigm(f2sum(az1)+bi[256+j1]+bh[256+j1]);
    float n0=tanhf(f2sum(an0)+bi[512+j0]+r0*bh[512+j0]);
    float n1=tanhf(f2sum(an1)+bi[512+j1]+r1*bh[512+j1]);
    *(float2*)&g_h2b[b*256+j0]=make_float2((1.f-z0)*n0,(1.f-z1)*n1);
}

// ===== head =====
__global__ void gru_head(const float* __restrict__ W_out,
                         const float* __restrict__ b_out,float* __restrict__ out){
    const int b=blockIdx.x, tid=threadIdx.x;
    float a0=0,a1=0,a2=0;
    for(int k=tid;k<Hsz;k+=128){
        float v=g_h2f[b*Hsz+k]+g_h2b[b*Hsz+k];
        a0+=v*W_out[k];a1+=v*W_out[256+k];a2+=v*W_out[512+k];
    }
    #pragma unroll
    for(int o=16;o>0;o>>=1){
        a0+=__shfl_xor_sync(0xffffffffu,a0,o);
        a1+=__shfl_xor_sync(0xffffffffu,a1,o);
        a2+=__shfl_xor_sync(0xffffffffu,a2,o);
    }
    __shared__ float red[3][4];
    if((tid&31)==0){int w=tid>>5;red[0][w]=a0;red[1][w]=a1;red[2][w]=a2;}
    __syncthreads();
    if(tid==0){
        a0=red[0][0]+red[0][1]+red[0][2]+red[0][3]+b_out[0];
        a1=red[1][0]+red[1][1]+red[1][2]+red[1][3]+b_out[1];
        a2=red[2][0]+red[2][1]+red[2][2]+red[2][3]+b_out[2];
        float m=fmaxf(a0,fmaxf(a1,a2));
        float e0=expf(a0-m),e1=expf(a1-m),e2=expf(a2-m);
        float inv=1.f/(e0+e1+e2);
        out[b*3+0]=e0*inv;out[b*3+1]=e1*inv;out[b*3+2]=e2*inv;
    }
}

extern "C" void kernel_launch(void* const* d_in,const int* in_sizes,int n_in,
                              void* d_out,int out_size){
    const float* x=(const float*)d_in[0];
    const float* Wih0=(const float*)d_in[1];
    const float* Whh0=(const float*)d_in[2];
    const float* bih0=(const float*)d_in[3];
    const float* bhh0=(const float*)d_in[4];
    const float* Wih1=(const float*)d_in[5];
    const float* Whh1=(const float*)d_in[6];
    const float* bih1=(const float*)d_in[7];
    const float* bhh1=(const float*)d_in[8];
    const float* W_out=(const float*)d_in[9];
    const float* b_out=(const float*)d_in[10];
    float* out=(float*)d_out;

    const int sm0=196608+16384;   // 212,992
    const int sm1=196608+8192;    // 204,800
    cudaFuncSetAttribute(gru0,cudaFuncAttributeMaxDynamicSharedMemorySize,sm0);
    cudaFuncSetAttribute(gru1,cudaFuncAttributeMaxDynamicSharedMemorySize,sm1);

    gru0<<<128,256,sm0>>>(x,Wih0,Whh0,bih0,bhh0);
    xpg<<<dim3(12,1024),256>>>(Wih1);
    g1bwd<<<128,256>>>(Wih1,bih1,bhh1);
    gru1<<<128,256,sm1>>>(Whh1,bih1,bhh1);
    gru_head<<<256,128>>>(W_out,b_out,out);
}

// round 10
// speedup vs baseline: 1.6588x; 1.0711x over previous
#include <cuda_runtime.h>
#include <math.h>

#define Tsz 256
#define Hsz 256

__device__ float g_h1[(size_t)256*256*512];     // layer-0 output [b][t][512]
__device__ float g_xp[(size_t)65536*768];       // layer-1 x-projection
__device__ float g_h2f[256*256];
__device__ float g_h2b[256*256];

typedef unsigned long long u64;
__device__ __forceinline__ u64 ffma2(u64 a,u64 b,u64 c){u64 d;asm("fma.rn.f32x2 %0,%1,%2,%3;":"=l"(d):"l"(a),"l"(b),"l"(c));return d;}
__device__ __forceinline__ u64 dup2(float v){u64 d;asm("mov.b64 %0,{%1,%2};":"=l"(d):"f"(v),"f"(v));return d;}
__device__ __forceinline__ u64 pk2(float a,float b){u64 d;asm("mov.b64 %0,{%1,%2};":"=l"(d):"f"(a),"f"(b));return d;}
__device__ __forceinline__ float lo2(u64 v){return __uint_as_float((unsigned)v);}
__device__ __forceinline__ float hi2(u64 v){return __uint_as_float((unsigned)(v>>32));}
__device__ __forceinline__ float f2sum(u64 v){return lo2(v)+hi2(v);}
__device__ __forceinline__ float sigm(float v){return 1.f/(1.f+__expf(-v));}

__device__ __forceinline__ unsigned smaddr(const void* p){unsigned a;
    asm("{.reg .u64 t; cvta.to.shared.u64 t,%1; cvt.u32.u64 %0,t;}":"=r"(a):"l"(p));return a;}
__device__ __forceinline__ unsigned mapar(unsigned a,unsigned r){unsigned o;
    asm("mapa.shared::cluster.u32 %0,%1,%2;":"=r"(o):"r"(a),"r"(r));return o;}
__device__ __forceinline__ void stc64(unsigned a,u64 v){
    asm volatile("st.shared::cluster.b64 [%0],%1;"::"r"(a),"l"(v):"memory");}
#define CSYNC() do{asm volatile("barrier.cluster.arrive.aligned;":::"memory"); \
                   asm volatile("barrier.cluster.wait.aligned;":::"memory");}while(0)

// ===== layer 0: 32 clusters x 4 CTAs; cluster = 16 seqs of one dir.
// CTA rank q owns j-quarter [64q,64q+64). Thread: 2 seqs x j-pair.
// smem: wrz [256k][32jp] ulonglong2 (128KB) + wn [256k][32jp] u64 (64KB)
//       + hs double-buffered [2][256 hid][16 seq] f32 (32KB)  = 229,376 B
__global__ void __launch_bounds__(256,1) __cluster_dims__(4,1,1) gru0(
    const float* __restrict__ x,const float* __restrict__ Wih0,
    const float* __restrict__ Whh0,const float* __restrict__ bih0,
    const float* __restrict__ bhh0)
{
    extern __shared__ __align__(16) unsigned char smraw[];
    ulonglong2* wrz=(ulonglong2*)smraw;          // 8192 * 16B
    u64* wn=(u64*)(smraw+131072);                // 8192 * 8B
    float* hs=(float*)(smraw+196608);            // 2 * 4096 f32
    unsigned q; asm("mov.u32 %0,%%cluster_ctarank;":"=r"(q));
    const int cid=blockIdx.x>>2;
    const int dir=cid>>4, bbase=(cid&15)*16;
    const int tid=threadIdx.x, w=tid>>5, lane=tid&31;
    const int jp=(lane&7)|((w&3)<<3);
    const int sg=(lane>>3)|((w>>2)<<2);
    const int j0=q*64+2*jp, j1=j0+1;

    const float* Whh=Whh0+(size_t)dir*768*256;
    for(int i=tid;i<8192;i+=256){                // i = k*32 + p
        int k=i>>5,p=i&31,jj=q*64+2*p;
        ulonglong2 rz;
        rz.x=pk2(Whh[(size_t)(0*256+jj)*256+k],Whh[(size_t)(0*256+jj+1)*256+k]);
        rz.y=pk2(Whh[(size_t)(1*256+jj)*256+k],Whh[(size_t)(1*256+jj+1)*256+k]);
        wrz[i]=rz;
        wn[i]=pk2(Whh[(size_t)(2*256+jj)*256+k],Whh[(size_t)(2*256+jj+1)*256+k]);
    }
    const float* Wih=Wih0+(size_t)dir*768*4;
    const float4 wxr0=*(const float4*)&Wih[(0*256+j0)*4], wxr1=*(const float4*)&Wih[(0*256+j1)*4];
    const float4 wxz0=*(const float4*)&Wih[(1*256+j0)*4], wxz1=*(const float4*)&Wih[(1*256+j1)*4];
    const float4 wxn0=*(const float4*)&Wih[(2*256+j0)*4], wxn1=*(const float4*)&Wih[(2*256+j1)*4];
    const float* bi=bih0+dir*768; const float* bh=bhh0+dir*768;
    const float cr0=bi[j0],cr1=bi[j1],cz0=bi[256+j0],cz1=bi[256+j1],cn0=bi[512+j0],cn1=bi[512+j1];
    const float br0=bh[j0],br1=bh[j1],bz0=bh[256+j0],bz1=bh[256+j1],bn0=bh[512+j0],bn1=bh[512+j1];

    for(int i=tid;i<8192;i+=256)hs[i]=0.f;
    unsigned hsa=smaddr(hs);
    unsigned peer[4];
    #pragma unroll
    for(int r=0;r<4;r++)peer[r]=mapar(hsa,r);
    __syncthreads();
    CSYNC();    // all weights + zeroed h visible cluster-wide

    const int s0=2*sg, s1=s0+1;
    const int bg0=bbase+s0, bg1=bbase+s1;

    for(int s=0;s<Tsz;s++){
        const int t=dir?255-s:s;
        const int cur=s&1;
        const u64* hk=(const u64*)(hs+cur*4096);
        u64 aR0=0,aZ0=0,aN0=0,aR1=0,aZ1=0,aN1=0;
        #pragma unroll 8
        for(int k=0;k<256;k++){
            u64 h2=hk[k*8+sg];
            u64 hA=dup2(lo2(h2)),hB=dup2(hi2(h2));
            ulonglong2 rz=wrz[k*32+jp];
            u64 nn=wn[k*32+jp];
            aR0=ffma2(hA,rz.x,aR0); aZ0=ffma2(hA,rz.y,aZ0); aN0=ffma2(hA,nn,aN0);
            aR1=ffma2(hB,rz.x,aR1); aZ1=ffma2(hB,rz.y,aZ1); aN1=ffma2(hB,nn,aN1);
        }
        float4 xv0=((const float4*)x)[(size_t)bg0*256+t];
        float4 xv1=((const float4*)x)[(size_t)bg1*256+t];
        const float* hc=hs+cur*4096;
        float hp00=hc[j0*16+s0],hp01=hc[j1*16+s0];
        float hp10=hc[j0*16+s1],hp11=hc[j1*16+s1];

        float xr0=cr0+xv0.x*wxr0.x+xv0.y*wxr0.y+xv0.z*wxr0.z+xv0.w*wxr0.w;
        float xr1=cr1+xv0.x*wxr1.x+xv0.y*wxr1.y+xv0.z*wxr1.z+xv0.w*wxr1.w;
        float xz0=cz0+xv0.x*wxz0.x+xv0.y*wxz0.y+xv0.z*wxz0.z+xv0.w*wxz0.w;
        float xz1=cz1+xv0.x*wxz1.x+xv0.y*wxz1.y+xv0.z*wxz1.z+xv0.w*wxz1.w;
        float xn0=cn0+xv0.x*wxn0.x+xv0.y*wxn0.y+xv0.z*wxn0.z+xv0.w*wxn0.w;
        float xn1=cn1+xv0.x*wxn1.x+xv0.y*wxn1.y+xv0.z*wxn1.z+xv0.w*wxn1.w;
        float r0=sigm(xr0+lo2(aR0)+br0), r1=sigm(xr1+hi2(aR0)+br1);
        float z0=sigm(xz0+lo2(aZ0)+bz0), z1=sigm(xz1+hi2(aZ0)+bz1);
        float n0=tanhf(xn0+r0*(lo2(aN0)+bn0)), n1=tanhf(xn1+r1*(hi2(aN0)+bn1));
        float hA0=(1.f-z0)*n0+z0*hp00, hA1=(1.f-z1)*n1+z1*hp01;

        xr0=cr0+xv1.x*wxr0.x+xv1.y*wxr0.y+xv1.z*wxr0.z+xv1.w*wxr0.w;
        xr1=cr1+xv1.x*wxr1.x+xv1.y*wxr1.y+xv1.z*wxr1.z+xv1.w*wxr1.w;
        xz0=cz0+xv1.x*wxz0.x+xv1.y*wxz0.y+xv1.z*wxz0.z+xv1.w*wxz0.w;
        xz1=cz1+xv1.x*wxz1.x+xv1.y*wxz1.y+xv1.z*wxz1.z+xv1.w*wxz1.w;
        xn0=cn0+xv1.x*wxn0.x+xv1.y*wxn0.y+xv1.z*wxn0.z+xv1.w*wxn0.w;
        xn1=cn1+xv1.x*wxn1.x+xv1.y*wxn1.y+xv1.z*wxn1.z+xv1.w*wxn1.w;
        r0=sigm(xr0+lo2(aR1)+br0); r1=sigm(xr1+hi2(aR1)+br1);
        z0=sigm(xz0+lo2(aZ1)+bz0); z1=sigm(xz1+hi2(aZ1)+bz1);
        n0=tanhf(xn0+r0*(lo2(aN1)+bn0)); n1=tanhf(xn1+r1*(hi2(aN1)+bn1));
        float hB0=(1.f-z0)*n0+z0*hp10, hB1=(1.f-z1)*n1+z1*hp11;

        // write next-step h (buffer cur^1) to all peers: packed (seq s0, seq s1)
        const unsigned nxtb=(unsigned)((cur^1)*16384);
        u64 pj0=pk2(hA0,hB0), pj1=pk2(hA1,hB1);
        #pragma unroll
        for(int r=0;r<4;r++){
            unsigned pb=peer[r]+nxtb;
            stc64(pb+(unsigned)(j0*16+s0)*4,pj0);
            stc64(pb+(unsigned)(j1*16+s0)*4,pj1);
        }
        *(float2*)&g_h1[((size_t)bg0*256+t)*512+dir*256+j0]=make_float2(hA0,hA1);
        *(float2*)&g_h1[((size_t)bg1*256+t)*512+dir*256+j0]=make_float2(hB0,hB1);
        CSYNC();
    }
}

// ===== xp GEMM: g_xp[m][n] = g_h1[m][k] * Wih1[0][n][k], m=65536,n=768,k=512
__global__ void __launch_bounds__(256,2) xpg(const float* __restrict__ W){
    __shared__ float As[2][16][68], Bs[2][16][68];
    const int bn=blockIdx.x, bm=blockIdx.y;
    const int tid=threadIdx.x, tx=tid&15, ty=tid>>4;
    const int r=tid>>2, s=tid&3;
    const float* Ar=g_h1+(size_t)(bm*64+r)*512+4*s;
    const float* Br=W+(size_t)(bn*64+r)*512+4*s;
    u64 acc[4][2]={};
    float4 a=*(const float4*)Ar, b=*(const float4*)Br;
    As[0][4*s+0][r]=a.x;As[0][4*s+1][r]=a.y;As[0][4*s+2][r]=a.z;As[0][4*s+3][r]=a.w;
    Bs[0][4*s+0][r]=b.x;Bs[0][4*s+1][r]=b.y;Bs[0][4*s+2][r]=b.z;Bs[0][4*s+3][r]=b.w;
    __syncthreads();
    for(int kt=0;kt<32;kt++){
        const int buf=kt&1;
        if(kt<31){a=*(const float4*)(Ar+(kt+1)*16);b=*(const float4*)(Br+(kt+1)*16);}
        #pragma unroll
        for(int k=0;k<16;k++){
            float4 av=*(const float4*)&As[buf][k][4*ty];
            ulonglong2 bv=*(const ulonglong2*)&Bs[buf][k][4*tx];
            u64 a0=dup2(av.x),a1=dup2(av.y),a2=dup2(av.z),a3=dup2(av.w);
            acc[0][0]=ffma2(a0,bv.x,acc[0][0]); acc[0][1]=ffma2(a0,bv.y,acc[0][1]);
            acc[1][0]=ffma2(a1,bv.x,acc[1][0]); acc[1][1]=ffma2(a1,bv.y,acc[1][1]);
            acc[2][0]=ffma2(a2,bv.x,acc[2][0]); acc[2][1]=ffma2(a2,bv.y,acc[2][1]);
            acc[3][0]=ffma2(a3,bv.x,acc[3][0]); acc[3][1]=ffma2(a3,bv.y,acc[3][1]);
        }
        if(kt<31){
            const int nb=1-buf;
            As[nb][4*s+0][r]=a.x;As[nb][4*s+1][r]=a.y;As[nb][4*s+2][r]=a.z;As[nb][4*s+3][r]=a.w;
            Bs[nb][4*s+0][r]=b.x;Bs[nb][4*s+1][r]=b.y;Bs[nb][4*s+2][r]=b.z;Bs[nb][4*s+3][r]=b.w;
        }
        __syncthreads();
    }
    float* o=g_xp+(size_t)(bm*64+ty*4)*768+bn*64+tx*4;
    #pragma unroll
    for(int m=0;m<4;m++){
        *(float2*)(o+(size_t)m*768)  =make_float2(lo2(acc[m][0]),hi2(acc[m][0]));
        *(float2*)(o+(size_t)m*768+2)=make_float2(lo2(acc[m][1]),hi2(acc[m][1]));
    }
}

// ===== layer 1 fwd scan: 32 clusters x 4 CTAs, 8 seqs/cluster, K=256 only.
// h stored PRE-SPLATTED (u64 per value): inner loop = 3 LDS + 3 ffma2.
// smem: wrz 128KB + wn 64KB + hs2 [2][256 j][8 seq] u64 (32KB) = 229,376 B
__global__ void __launch_bounds__(256,1) __cluster_dims__(4,1,1) gru1(
    const float* __restrict__ Whh1,const float* __restrict__ bih1,
    const float* __restrict__ bhh1)
{
    extern __shared__ __align__(16) unsigned char smraw[];
    ulonglong2* wrz=(ulonglong2*)smraw;
    u64* wn=(u64*)(smraw+131072);
    u64* hs2=(u64*)(smraw+196608);
    unsigned q; asm("mov.u32 %0,%%cluster_ctarank;":"=r"(q));
    const int cid=blockIdx.x>>2;
    const int tid=threadIdx.x, w=tid>>5, lane=tid&31;
    const int jp=(lane&7)|((w&3)<<3);
    const int sq=(lane>>3)|((w>>2)<<2);
    const int j0=q*64+2*jp, j1=j0+1;
    const int b=cid*8+sq;

    for(int i=tid;i<8192;i+=256){
        int k=i>>5,p=i&31,jj=q*64+2*p;
        ulonglong2 rz;
        rz.x=pk2(Whh1[(size_t)(0*256+jj)*256+k],Whh1[(size_t)(0*256+jj+1)*256+k]);
        rz.y=pk2(Whh1[(size_t)(1*256+jj)*256+k],Whh1[(size_t)(1*256+jj+1)*256+k]);
        wrz[i]=rz;
        wn[i]=pk2(Whh1[(size_t)(2*256+jj)*256+k],Whh1[(size_t)(2*256+jj+1)*256+k]);
    }
    const float cr0=bih1[j0]+bhh1[j0],         cr1=bih1[j1]+bhh1[j1];
    const float cz0=bih1[256+j0]+bhh1[256+j0], cz1=bih1[256+j1]+bhh1[256+j1];
    const float cx0=bih1[512+j0], cx1=bih1[512+j1];
    const float cn0=bhh1[512+j0], cn1=bhh1[512+j1];

    for(int i=tid;i<4096;i+=256)hs2[i]=0ull;
    unsigned hsa=smaddr(hs2);
    unsigned peer[4];
    #pragma unroll
    for(int r=0;r<4;r++)peer[r]=mapar(hsa,r);
    __syncthreads();
    CSYNC();

    for(int t=0;t<Tsz;t++){
        const int cur=t&1;
        const u64* hk=hs2+cur*2048;
        u64 aR=0,aZ=0,aN=0;
        #pragma unroll 8
        for(int k=0;k<256;k++){
            u64 hv=hk[k*8+sq];
            ulonglong2 rz=wrz[k*32+jp];
            aR=ffma2(hv,rz.x,aR); aZ=ffma2(hv,rz.y,aZ); aN=ffma2(hv,wn[k*32+jp],aN);
        }
        const float* xr_=&g_xp[(size_t)(b*256+t)*768];
        float2 pr=__ldg((const float2*)(xr_+j0));
        float2 pz=__ldg((const float2*)(xr_+256+j0));
        float2 pn=__ldg((const float2*)(xr_+512+j0));
        float hp0=lo2(hk[j0*8+sq]), hp1=lo2(hk[j1*8+sq]);
        float r0=sigm(pr.x+lo2(aR)+cr0), r1=sigm(pr.y+hi2(aR)+cr1);
        float z0=sigm(pz.x+lo2(aZ)+cz0), z1=sigm(pz.y+hi2(aZ)+cz1);
        float n0=tanhf(pn.x+cx0+r0*(lo2(aN)+cn0));
        float n1=tanhf(pn.y+cx1+r1*(hi2(aN)+cn1));
        float h0=(1.f-z0)*n0+z0*hp0, h1=(1.f-z1)*n1+z1*hp1;

        const unsigned nxtb=(unsigned)((cur^1)*16384);
        u64 s0=dup2(h0), s1=dup2(h1);
        #pragma unroll
        for(int r=0;r<4;r++){
            unsigned pb=peer[r]+nxtb;
            stc64(pb+(unsigned)(j0*8+sq)*8,s0);
            stc64(pb+(unsigned)(j1*8+sq)*8,s1);
        }
        if(t==255)*(float2*)&g_h2f[b*256+j0]=make_float2(h0,h1);
        CSYNC();
    }
}

// ===== layer 1 single bwd step (h=0): pure x-projection with Wih1[1].
__global__ void __launch_bounds__(256,1) g1bwd(
    const float* __restrict__ Wih1,const float* __restrict__ bih1,
    const float* __restrict__ bhh1)
{
    const int bt=blockIdx.x>>4, jt=blockIdx.x&15;
    const int tid=threadIdx.x, bl=tid>>3, jp=tid&7;
    const int b=bt*32+bl, j0=jt*16+2*jp, j1=j0+1;
    const float* W=Wih1+(size_t)768*512;
    const float2* xp=(const float2*)&g_h1[((size_t)b*256+255)*512];
    const float2* wr0=(const float2*)&W[(size_t)(0*256+j0)*512];
    const float2* wr1=(const float2*)&W[(size_t)(0*256+j1)*512];
    const float2* wz0=(const float2*)&W[(size_t)(1*256+j0)*512];
    const float2* wz1=(const float2*)&W[(size_t)(1*256+j1)*512];
    const float2* wn0=(const float2*)&W[(size_t)(2*256+j0)*512];
    const float2* wn1=(const float2*)&W[(size_t)(2*256+j1)*512];
    u64 ar0=0,ar1=0,az0=0,az1=0,an0=0,an1=0;
    #pragma unroll 8
    for(int k2=0;k2<256;k2++){
        float2 xv=__ldg(&xp[k2]); u64 xu=pk2(xv.x,xv.y);
        float2 t0=__ldg(&wr0[k2]); ar0=ffma2(xu,pk2(t0.x,t0.y),ar0);
        float2 t1=__ldg(&wr1[k2]); ar1=ffma2(xu,pk2(t1.x,t1.y),ar1);
        float2 t2=__ldg(&wz0[k2]); az0=ffma2(xu,pk2(t2.x,t2.y),az0);
        float2 t3=__ldg(&wz1[k2]); az1=ffma2(xu,pk2(t3.x,t3.y),az1);
        float2 t4=__ldg(&wn0[k2]); an0=ffma2(xu,pk2(t4.x,t4.y),an0);
        float2 t5=__ldg(&wn1[k2]); an1=ffma2(xu,pk2(t5.x,t5.y),an1);
    }
    const float* bi=bih1+768; const float* bh=bhh1+768;
    float r0=sigm(f2sum(ar0)+bi[j0]+bh[j0]);
    float r1=sigm(f2sum(ar1)+bi[j1]+bh[j1]);
    float z0=sigm(f2sum(az0)+bi[256+j0]+bh[256+j0]);
    float z1=sigm(f2sum(az1)+bi[256+j1]+bh[256+j1]);
    float n0=tanhf(f2sum(an0)+bi[512+j0]+r0*bh[512+j0]);
    float n1=tanhf(f2sum(an1)+bi[512+j1]+r1*bh[512+j1]);
    *(float2*)&g_h2b[b*256+j0]=make_float2((1.f-z0)*n0,(1.f-z1)*n1);
}

// ===== head =====
__global__ void gru_head(const float* __restrict__ W_out,
                         const float* __restrict__ b_out,float* __restrict__ out){
    const int b=blockIdx.x, tid=threadIdx.x;
    float a0=0,a1=0,a2=0;
    for(int k=tid;k<Hsz;k+=128){
        float v=g_h2f[b*Hsz+k]+g_h2b[b*Hsz+k];
        a0+=v*W_out[k];a1+=v*W_out[256+k];a2+=v*W_out[512+k];
    }
    #pragma unroll
    for(int o=16;o>0;o>>=1){
        a0+=__shfl_xor_sync(0xffffffffu,a0,o);
        a1+=__shfl_xor_sync(0xffffffffu,a1,o);
        a2+=__shfl_xor_sync(0xffffffffu,a2,o);
    }
    __shared__ float red[3][4];
    if((tid&31)==0){int w=tid>>5;red[0][w]=a0;red[1][w]=a1;red[2][w]=a2;}
    __syncthreads();
    if(tid==0){
        a0=red[0][0]+red[0][1]+red[0][2]+red[0][3]+b_out[0];
        a1=red[1][0]+red[1][1]+red[1][2]+red[1][3]+b_out[1];
        a2=red[2][0]+red[2][1]+red[2][2]+red[2][3]+b_out[2];
        float m=fmaxf(a0,fmaxf(a1,a2));
        float e0=expf(a0-m),e1=expf(a1-m),e2=expf(a2-m);
        float inv=1.f/(e0+e1+e2);
        out[b*3+0]=e0*inv;out[b*3+1]=e1*inv;out[b*3+2]=e2*inv;
    }
}

extern "C" void kernel_launch(void* const* d_in,const int* in_sizes,int n_in,
                              void* d_out,int out_size){
    const float* x=(const float*)d_in[0];
    const float* Wih0=(const float*)d_in[1];
    const float* Whh0=(const float*)d_in[2];
    const float* bih0=(const float*)d_in[3];
    const float* bhh0=(const float*)d_in[4];
    const float* Wih1=(const float*)d_in[5];
    const float* Whh1=(const float*)d_in[6];
    const float* bih1=(const float*)d_in[7];
    const float* bhh1=(const float*)d_in[8];
    const float* W_out=(const float*)d_in[9];
    const float* b_out=(const float*)d_in[10];
    float* out=(float*)d_out;

    const int sm0=196608+32768;   // 229,376
    const int sm1=196608+32768;   // 229,376
    cudaFuncSetAttribute(gru0,cudaFuncAttributeMaxDynamicSharedMemorySize,sm0);
    cudaFuncSetAttribute(gru1,cudaFuncAttributeMaxDynamicSharedMemorySize,sm1);

    gru0<<<128,256,sm0>>>(x,Wih0,Whh0,bih0,bhh0);
    xpg<<<dim3(12,1024),256>>>(Wih1);
    g1bwd<<<128,256>>>(Wih1,bih1,bhh1);
    gru1<<<128,256,sm1>>>(Whh1,bih1,bhh1);
    gru_head<<<256,128>>>(W_out,b_out,out);
}

// round 12
// speedup vs baseline: 1.7267x; 1.0409x over previous
#include <cuda_runtime.h>
#include <cuda_bf16.h>
#include <mma.h>
#include <math.h>
using namespace nvcuda;

#define Tsz 256
#define Hsz 256

__device__ float g_h1[(size_t)256*256*512];
__device__ float g_xp[(size_t)65536*768];
__device__ float g_h2f[256*256];
__device__ float g_h2b[256*256];
__device__ __nv_bfloat16 g_ab[(size_t)65536*1536];  // A' = [xh|xl|xh]
__device__ __nv_bfloat16 g_bb[(size_t)768*1536];    // B' = [Wh|Wh|Wl]

typedef unsigned long long u64;
__device__ __forceinline__ u64 ffma2(u64 a,u64 b,u64 c){u64 d;asm("fma.rn.f32x2 %0,%1,%2,%3;":"=l"(d):"l"(a),"l"(b),"l"(c));return d;}
__device__ __forceinline__ u64 dup2(float v){u64 d;asm("mov.b64 %0,{%1,%2};":"=l"(d):"f"(v),"f"(v));return d;}
__device__ __forceinline__ u64 pk2(float a,float b){u64 d;asm("mov.b64 %0,{%1,%2};":"=l"(d):"f"(a),"f"(b));return d;}
__device__ __forceinline__ float lo2(u64 v){return __uint_as_float((unsigned)v);}
__device__ __forceinline__ float hi2(u64 v){return __uint_as_float((unsigned)(v>>32));}
__device__ __forceinline__ float f2sum(u64 v){return lo2(v)+hi2(v);}
__device__ __forceinline__ float sigm(float v){return __fdividef(1.f,1.f+__expf(-v));}
__device__ __forceinline__ float tanhf_(float v){float e=__expf(2.f*v);return 1.f-__fdividef(2.f,e+1.f);}

__device__ __forceinline__ unsigned smaddr(const void* p){unsigned a;
    asm("{.reg .u64 t; cvta.to.shared.u64 t,%1; cvt.u32.u64 %0,t;}":"=r"(a):"l"(p));return a;}
__device__ __forceinline__ unsigned mapar(unsigned a,unsigned r){unsigned o;
    asm("mapa.shared::cluster.u32 %0,%1,%2;":"=r"(o):"r"(a),"r"(r));return o;}
__device__ __forceinline__ void stc64(unsigned a,u64 v){
    asm volatile("st.shared::cluster.b64 [%0],%1;"::"r"(a),"l"(v):"memory");}
#define CSYNC() do{asm volatile("barrier.cluster.arrive.aligned;":::"memory"); \
                   asm volatile("barrier.cluster.wait.aligned;":::"memory");}while(0)

// ===== layer 0 scan ========================================================
__global__ void __launch_bounds__(256,1) __cluster_dims__(4,1,1) gru0(
    const float* __restrict__ x,const float* __restrict__ Wih0,
    const float* __restrict__ Whh0,const float* __restrict__ bih0,
    const float* __restrict__ bhh0)
{
    extern __shared__ __align__(16) unsigned char smraw[];
    ulonglong2* wrz=(ulonglong2*)smraw;
    u64* wn=(u64*)(smraw+131072);
    float* hs=(float*)(smraw+196608);
    unsigned q; asm("mov.u32 %0,%%cluster_ctarank;":"=r"(q));
    const int cid=blockIdx.x>>2;
    const int dir=cid>>4, bbase=(cid&15)*16;
    const int tid=threadIdx.x, w=tid>>5, lane=tid&31;
    const int jp=(lane&7)|((w&3)<<3);
    const int sg=(lane>>3)|((w>>2)<<2);
    const int j0=q*64+2*jp, j1=j0+1;

    const float* Whh=Whh0+(size_t)dir*768*256;
    for(int i=tid;i<8192;i+=256){
        int k=i>>5,p=i&31,jj=q*64+2*p;
        ulonglong2 rz;
        rz.x=pk2(Whh[(size_t)(0*256+jj)*256+k],Whh[(size_t)(0*256+jj+1)*256+k]);
        rz.y=pk2(Whh[(size_t)(1*256+jj)*256+k],Whh[(size_t)(1*256+jj+1)*256+k]);
        wrz[i]=rz;
        wn[i]=pk2(Whh[(size_t)(2*256+jj)*256+k],Whh[(size_t)(2*256+jj+1)*256+k]);
    }
    const float* Wih=Wih0+(size_t)dir*768*4;
    const float4 wxr0=*(const float4*)&Wih[(0*256+j0)*4], wxr1=*(const float4*)&Wih[(0*256+j1)*4];
    const float4 wxz0=*(const float4*)&Wih[(1*256+j0)*4], wxz1=*(const float4*)&Wih[(1*256+j1)*4];
    const float4 wxn0=*(const float4*)&Wih[(2*256+j0)*4], wxn1=*(const float4*)&Wih[(2*256+j1)*4];
    const float* bi=bih0+dir*768; const float* bh=bhh0+dir*768;
    const float cr0=bi[j0],cr1=bi[j1],cz0=bi[256+j0],cz1=bi[256+j1],cn0=bi[512+j0],cn1=bi[512+j1];
    const float br0=bh[j0],br1=bh[j1],bz0=bh[256+j0],bz1=bh[256+j1],bn0=bh[512+j0],bn1=bh[512+j1];

    for(int i=tid;i<8192;i+=256)hs[i]=0.f;
    unsigned hsa=smaddr(hs);
    unsigned peer[4];
    #pragma unroll
    for(int r=0;r<4;r++)peer[r]=mapar(hsa,r);
    __syncthreads();
    CSYNC();

    const int s0=2*sg, s1=s0+1;
    const int bg0=bbase+s0, bg1=bbase+s1;

    for(int s=0;s<Tsz;s++){
        const int t=dir?255-s:s;
        const int cur=s&1;
        const u64* hk=(const u64*)(hs+cur*4096);
        u64 aR0=0,aZ0=0,aN0=0,aR1=0,aZ1=0,aN1=0;
        #pragma unroll 8
        for(int k=0;k<256;k++){
            u64 h2=hk[k*8+sg];
            u64 hA=dup2(lo2(h2)),hB=dup2(hi2(h2));
            ulonglong2 rz=wrz[k*32+jp];
            u64 nn=wn[k*32+jp];
            aR0=ffma2(hA,rz.x,aR0); aZ0=ffma2(hA,rz.y,aZ0); aN0=ffma2(hA,nn,aN0);
            aR1=ffma2(hB,rz.x,aR1); aZ1=ffma2(hB,rz.y,aZ1); aN1=ffma2(hB,nn,aN1);
        }
        float4 xv0=((const float4*)x)[(size_t)bg0*256+t];
        float4 xv1=((const float4*)x)[(size_t)bg1*256+t];
        const float* hc=hs+cur*4096;
        float hp00=hc[j0*16+s0],hp01=hc[j1*16+s0];
        float hp10=hc[j0*16+s1],hp11=hc[j1*16+s1];

        float xr0=cr0+xv0.x*wxr0.x+xv0.y*wxr0.y+xv0.z*wxr0.z+xv0.w*wxr0.w;
        float xr1=cr1+xv0.x*wxr1.x+xv0.y*wxr1.y+xv0.z*wxr1.z+xv0.w*wxr1.w;
        float xz0=cz0+xv0.x*wxz0.x+xv0.y*wxz0.y+xv0.z*wxz0.z+xv0.w*wxz0.w;
        float xz1=cz1+xv0.x*wxz1.x+xv0.y*wxz1.y+xv0.z*wxz1.z+xv0.w*wxz1.w;
        float xn0=cn0+xv0.x*wxn0.x+xv0.y*wxn0.y+xv0.z*wxn0.z+xv0.w*wxn0.w;
        float xn1=cn1+xv0.x*wxn1.x+xv0.y*wxn1.y+xv0.z*wxn1.z+xv0.w*wxn1.w;
        float r0=sigm(xr0+lo2(aR0)+br0), r1=sigm(xr1+hi2(aR0)+br1);
        float z0=sigm(xz0+lo2(aZ0)+bz0), z1=sigm(xz1+hi2(aZ0)+bz1);
        float n0=tanhf_(xn0+r0*(lo2(aN0)+bn0)), n1=tanhf_(xn1+r1*(hi2(aN0)+bn1));
        float hA0=(1.f-z0)*n0+z0*hp00, hA1=(1.f-z1)*n1+z1*hp01;

        xr0=cr0+xv1.x*wxr0.x+xv1.y*wxr0.y+xv1.z*wxr0.z+xv1.w*wxr0.w;
        xr1=cr1+xv1.x*wxr1.x+xv1.y*wxr1.y+xv1.z*wxr1.z+xv1.w*wxr1.w;
        xz0=cz0+xv1.x*wxz0.x+xv1.y*wxz0.y+xv1.z*wxz0.z+xv1.w*wxz0.w;
        xz1=cz1+xv1.x*wxz1.x+xv1.y*wxz1.y+xv1.z*wxz1.z+xv1.w*wxz1.w;
        xn0=cn0+xv1.x*wxn0.x+xv1.y*wxn0.y+xv1.z*wxn0.z+xv1.w*wxn0.w;
        xn1=cn1+xv1.x*wxn1.x+xv1.y*wxn1.y+xv1.z*wxn1.z+xv1.w*wxn1.w;
        r0=sigm(xr0+lo2(aR1)+br0); r1=sigm(xr1+hi2(aR1)+br1);
        z0=sigm(xz0+lo2(aZ1)+bz0); z1=sigm(xz1+hi2(aZ1)+bz1);
        n0=tanhf_(xn0+r0*(lo2(aN1)+bn0)); n1=tanhf_(xn1+r1*(hi2(aN1)+bn1));
        float hB0=(1.f-z0)*n0+z0*hp10, hB1=(1.f-z1)*n1+z1*hp11;

        const unsigned nxtb=(unsigned)((cur^1)*16384);
        u64 pj0=pk2(hA0,hB0), pj1=pk2(hA1,hB1);
        #pragma unroll
        for(int r=0;r<4;r++){
            unsigned pb=peer[r]+nxtb;
            stc64(pb+(unsigned)(j0*16+s0)*4,pj0);
            stc64(pb+(unsigned)(j1*16+s0)*4,pj1);
        }
        *(float2*)&g_h1[((size_t)bg0*256+t)*512+dir*256+j0]=make_float2(hA0,hA1);
        *(float2*)&g_h1[((size_t)bg1*256+t)*512+dir*256+j0]=make_float2(hB0,hB1);
        CSYNC();
    }
}

// ===== conversions =========================================================
__global__ void convW(const float* __restrict__ Wih1){
    const int n=blockIdx.x, k=threadIdx.x;
    float w=Wih1[(size_t)n*512+k];
    __nv_bfloat16 hi=__float2bfloat16(w);
    __nv_bfloat16 lo=__float2bfloat16(w-__bfloat162float(hi));
    g_bb[(size_t)n*1536+k]=hi;
    g_bb[(size_t)n*1536+512+k]=hi;
    g_bb[(size_t)n*1536+1024+k]=lo;
}
__global__ void convA(){
    const size_t m=blockIdx.x; const int k=threadIdx.x;
    float v=g_h1[m*512+k];
    __nv_bfloat16 hi=__float2bfloat16(v);
    __nv_bfloat16 lo=__float2bfloat16(v-__bfloat162float(hi));
    g_ab[m*1536+k]=hi;
    g_ab[m*1536+512+k]=lo;
    g_ab[m*1536+1024+k]=hi;
}

// ===== xp GEMM via wmma bf16: M=65536, N=768, K=1536 =======================
// grid (6 bn, 512 bm), 256 thr. CTA tile 128x128; warp (4x2) tile 32x64.
#define LDM 48
__global__ void __launch_bounds__(256,2) xpw(){
    __shared__ __nv_bfloat16 As[128][LDM], Bs[128][LDM];
    const int bn=blockIdx.x, bm=blockIdx.y;
    const int tid=threadIdx.x, wid=tid>>5;
    const int wm=wid>>1, wnb=wid&1;
    wmma::fragment<wmma::accumulator,16,16,16,float> acc[2][4];
    #pragma unroll
    for(int i=0;i<2;i++)
        #pragma unroll
        for(int j=0;j<4;j++)wmma::fill_fragment(acc[i][j],0.f);

    for(int kc=0;kc<48;kc++){
        __syncthreads();
        for(int i=tid;i<512;i+=256){
            int r=i>>2,g=i&3;
            *(float4*)&As[r][g*8]=*(const float4*)&g_ab[(size_t)(bm*128+r)*1536+kc*32+g*8];
        }
        for(int i=tid;i<512;i+=256){
            int r=i>>2,g=i&3;
            *(float4*)&Bs[r][g*8]=*(const float4*)&g_bb[(size_t)(bn*128+r)*1536+kc*32+g*8];
        }
        __syncthreads();
        #pragma unroll
        for(int kk=0;kk<2;kk++){
            wmma::fragment<wmma::matrix_a,16,16,16,__nv_bfloat16,wmma::row_major> af[2];
            wmma::fragment<wmma::matrix_b,16,16,16,__nv_bfloat16,wmma::col_major> bf[4];
            #pragma unroll
            for(int i=0;i<2;i++)wmma::load_matrix_sync(af[i],&As[wm*32+i*16][kk*16],LDM);
            #pragma unroll
            for(int j=0;j<4;j++)wmma::load_matrix_sync(bf[j],&Bs[wnb*64+j*16][kk*16],LDM);
            #pragma unroll
            for(int i=0;i<2;i++)
                #pragma unroll
                for(int j=0;j<4;j++)wmma::mma_sync(acc[i][j],af[i],bf[j],acc[i][j]);
        }
    }
    #pragma unroll
    for(int i=0;i<2;i++)
        #pragma unroll
        for(int j=0;j<4;j++)
            wmma::store_matrix_sync(&g_xp[(size_t)(bm*128+wm*32+i*16)*768+bn*128+wnb*64+j*16],
                                    acc[i][j],768,wmma::mem_row_major);
}

// ===== layer 1 fwd scan ====================================================
__global__ void __launch_bounds__(256,1) __cluster_dims__(4,1,1) gru1(
    const float* __restrict__ Whh1,const float* __restrict__ bih1,
    const float* __restrict__ bhh1)
{
    extern __shared__ __align__(16) unsigned char smraw[];
    ulonglong2* wrz=(ulonglong2*)smraw;
    u64* wn=(u64*)(smraw+131072);
    u64* hs2=(u64*)(smraw+196608);
    unsigned q; asm("mov.u32 %0,%%cluster_ctarank;":"=r"(q));
    const int cid=blockIdx.x>>2;
    const int tid=threadIdx.x, w=tid>>5, lane=tid&31;
    const int jp=(lane&7)|((w&3)<<3);
    const int sq=(lane>>3)|((w>>2)<<2);
    const int j0=q*64+2*jp, j1=j0+1;
    const int b=cid*8+sq;

    for(int i=tid;i<8192;i+=256){
        int k=i>>5,p=i&31,jj=q*64+2*p;
        ulonglong2 rz;
        rz.x=pk2(Whh1[(size_t)(0*256+jj)*256+k],Whh1[(size_t)(0*256+jj+1)*256+k]);
        rz.y=pk2(Whh1[(size_t)(1*256+jj)*256+k],Whh1[(size_t)(1*256+jj+1)*256+k]);
        wrz[i]=rz;
        wn[i]=pk2(Whh1[(size_t)(2*256+jj)*256+k],Whh1[(size_t)(2*256+jj+1)*256+k]);
    }
    const float cr0=bih1[j0]+bhh1[j0],         cr1=bih1[j1]+bhh1[j1];
    const float cz0=bih1[256+j0]+bhh1[256+j0], cz1=bih1[256+j1]+bhh1[256+j1];
    const float cx0=bih1[512+j0], cx1=bih1[512+j1];
    const float cn0=bhh1[512+j0], cn1=bhh1[512+j1];

    for(int i=tid;i<4096;i+=256)hs2[i]=0ull;
    unsigned hsa=smaddr(hs2);
    unsigned peer[4];
    #pragma unroll
    for(int r=0;r<4;r++)peer[r]=mapar(hsa,r);
    __syncthreads();
    CSYNC();

    for(int t=0;t<Tsz;t++){
        const int cur=t&1;
        const u64* hk=hs2+cur*2048;
        u64 aR=0,aZ=0,aN=0;
        #pragma unroll 8
        for(int k=0;k<256;k++){
            u64 hv=hk[k*8+sq];
            ulonglong2 rz=wrz[k*32+jp];
            aR=ffma2(hv,rz.x,aR); aZ=ffma2(hv,rz.y,aZ); aN=ffma2(hv,wn[k*32+jp],aN);
        }
        const float* xr_=&g_xp[(size_t)(b*256+t)*768];
        float2 pr=__ldg((const float2*)(xr_+j0));
        float2 pz=__ldg((const float2*)(xr_+256+j0));
        float2 pn=__ldg((const float2*)(xr_+512+j0));
        float hp0=lo2(hk[j0*8+sq]), hp1=lo2(hk[j1*8+sq]);
        float r0=sigm(pr.x+lo2(aR)+cr0), r1=sigm(pr.y+hi2(aR)+cr1);
        float z0=sigm(pz.x+lo2(aZ)+cz0), z1=sigm(pz.y+hi2(aZ)+cz1);
        float n0=tanhf_(pn.x+cx0+r0*(lo2(aN)+cn0));
        float n1=tanhf_(pn.y+cx1+r1*(hi2(aN)+cn1));
        float h0=(1.f-z0)*n0+z0*hp0, h1=(1.f-z1)*n1+z1*hp1;

        const unsigned nxtb=(unsigned)((cur^1)*16384);
        u64 s0=dup2(h0), s1=dup2(h1);
        #pragma unroll
        for(int r=0;r<4;r++){
            unsigned pb=peer[r]+nxtb;
            stc64(pb+(unsigned)(j0*8+sq)*8,s0);
            stc64(pb+(unsigned)(j1*8+sq)*8,s1);
        }
        if(t==255)*(float2*)&g_h2f[b*256+j0]=make_float2(h0,h1);
        CSYNC();
    }
}

// ===== layer 1 single bwd step (h=0) =======================================
__global__ void __launch_bounds__(256,1) g1bwd(
    const float* __restrict__ Wih1,const float* __restrict__ bih1,
    const float* __restrict__ bhh1)
{
    const int bt=blockIdx.x>>4, jt=blockIdx.x&15;
    const int tid=threadIdx.x, bl=tid>>3, jp=tid&7;
    const int b=bt*32+bl, j0=jt*16+2*jp, j1=j0+1;
    const float* W=Wih1+(size_t)768*512;
    const float2* xp=(const float2*)&g_h1[((size_t)b*256+255)*512];
    const float2* wr0=(const float2*)&W[(size_t)(0*256+j0)*512];
    const float2* wr1=(const float2*)&W[(size_t)(0*256+j1)*512];
    const float2* wz0=(const float2*)&W[(size_t)(1*256+j0)*512];
    const float2* wz1=(const float2*)&W[(size_t)(1*256+j1)*512];
    const float2* wn0=(const float2*)&W[(size_t)(2*256+j0)*512];
    const float2* wn1=(const float2*)&W[(size_t)(2*256+j1)*512];
    u64 ar0=0,ar1=0,az0=0,az1=0,an0=0,an1=0;
    #pragma unroll 8
    for(int k2=0;k2<256;k2++){
        float2 xv=__ldg(&xp[k2]); u64 xu=pk2(xv.x,xv.y);
        float2 t0=__ldg(&wr0[k2]); ar0=ffma2(xu,pk2(t0.x,t0.y),ar0);
        float2 t1=__ldg(&wr1[k2]); ar1=ffma2(xu,pk2(t1.x,t1.y),ar1);
        float2 t2=__ldg(&wz0[k2]); az0=ffma2(xu,pk2(t2.x,t2.y),az0);
        float2 t3=__ldg(&wz1[k2]); az1=ffma2(xu,pk2(t3.x,t3.y),az1);
        float2 t4=__ldg(&wn0[k2]); an0=ffma2(xu,pk2(t4.x,t4.y),an0);
        float2 t5=__ldg(&wn1[k2]); an1=ffma2(xu,pk2(t5.x,t5.y),an1);
    }
    const float* bi=bih1+768; const float* bh=bhh1+768;
    float r0=sigm(f2sum(ar0)+bi[j0]+bh[j0]);
    float r1=sigm(f2sum(ar1)+bi[j1]+bh[j1]);
    float z0=sigm(f2sum(az0)+bi[256+j0]+bh[256+j0]);
    float z1=sigm(f2sum(az1)+bi[256+j1]+bh[256+j1]);
    float n0=tanhf_(f2sum(an0)+bi[512+j0]+r0*bh[512+j0]);
    float n1=tanhf_(f2sum(an1)+bi[512+j1]+r1*bh[512+j1]);
    *(float2*)&g_h2b[b*256+j0]=make_float2((1.f-z0)*n0,(1.f-z1)*n1);
}

// ===== head =====
__global__ void gru_head(const float* __restrict__ W_out,
                         const float* __restrict__ b_out,float* __restrict__ out){
    const int b=blockIdx.x, tid=threadIdx.x;
    float a0=0,a1=0,a2=0;
    for(int k=tid;k<Hsz;k+=128){
        float v=g_h2f[b*Hsz+k]+g_h2b[b*Hsz+k];
        a0+=v*W_out[k];a1+=v*W_out[256+k];a2+=v*W_out[512+k];
    }
    #pragma unroll
    for(int o=16;o>0;o>>=1){
        a0+=__shfl_xor_sync(0xffffffffu,a0,o);
        a1+=__shfl_xor_sync(0xffffffffu,a1,o);
        a2+=__shfl_xor_sync(0xffffffffu,a2,o);
    }
    __shared__ float red[3][4];
    if((tid&31)==0){int w=tid>>5;red[0][w]=a0;red[1][w]=a1;red[2][w]=a2;}
    __syncthreads();
    if(tid==0){
        a0=red[0][0]+red[0][1]+red[0][2]+red[0][3]+b_out[0];
        a1=red[1][0]+red[1][1]+red[1][2]+red[1][3]+b_out[1];
        a2=red[2][0]+red[2][1]+red[2][2]+red[2][3]+b_out[2];
        float m=fmaxf(a0,fmaxf(a1,a2));
        float e0=expf(a0-m),e1=expf(a1-m),e2=expf(a2-m);
        float inv=1.f/(e0+e1+e2);
        out[b*3+0]=e0*inv;out[b*3+1]=e1*inv;out[b*3+2]=e2*inv;
    }
}

extern "C" void kernel_launch(void* const* d_in,const int* in_sizes,int n_in,
                              void* d_out,int out_size){
    const float* x=(const float*)d_in[0];
    const float* Wih0=(const float*)d_in[1];
    const float* Whh0=(const float*)d_in[2];
    const float* bih0=(const float*)d_in[3];
    const float* bhh0=(const float*)d_in[4];
    const float* Wih1=(const float*)d_in[5];
    const float* Whh1=(const float*)d_in[6];
    const float* bih1=(const float*)d_in[7];
    const float* bhh1=(const float*)d_in[8];
    const float* W_out=(const float*)d_in[9];
    const float* b_out=(const float*)d_in[10];
    float* out=(float*)d_out;

    const int sm0=196608+32768;
    const int sm1=196608+32768;
    cudaFuncSetAttribute(gru0,cudaFuncAttributeMaxDynamicSharedMemorySize,sm0);
    cudaFuncSetAttribute(gru1,cudaFuncAttributeMaxDynamicSharedMemorySize,sm1);

    convW<<<768,512>>>(Wih1);
    gru0<<<128,256,sm0>>>(x,Wih0,Whh0,bih0,bhh0);
    convA<<<65536,512>>>();
    xpw<<<dim3(6,512),256>>>();
    g1bwd<<<128,256>>>(Wih1,bih1,bhh1);
    gru1<<<128,256,sm1>>>(Whh1,bih1,bhh1);
    gru_head<<<256,128>>>(W_out,b_out,out);
}

// round 13
// speedup vs baseline: 1.9105x; 1.1065x over previous
#include <cuda_runtime.h>
#include <cuda_bf16.h>
#include <mma.h>
#include <math.h>
using namespace nvcuda;

#define Tsz 256
#define Hsz 256

__device__ float g_h1[(size_t)256*512];             // only t=255 rows [b][512]
__device__ float g_xp[(size_t)65536*768];
__device__ float g_h2f[256*256];
__device__ float g_h2b[256*256];
__device__ __nv_bfloat16 g_ab[(size_t)65536*1536];  // A' = [xh|xl|xh]
__device__ __nv_bfloat16 g_bb[(size_t)768*1536];    // B' = [Wh|Wh|Wl]

typedef unsigned long long u64;
__device__ __forceinline__ u64 ffma2(u64 a,u64 b,u64 c){u64 d;asm("fma.rn.f32x2 %0,%1,%2,%3;":"=l"(d):"l"(a),"l"(b),"l"(c));return d;}
__device__ __forceinline__ u64 dup2(float v){u64 d;asm("mov.b64 %0,{%1,%2};":"=l"(d):"f"(v),"f"(v));return d;}
__device__ __forceinline__ u64 pk2(float a,float b){u64 d;asm("mov.b64 %0,{%1,%2};":"=l"(d):"f"(a),"f"(b));return d;}
__device__ __forceinline__ float lo2(u64 v){return __uint_as_float((unsigned)v);}
__device__ __forceinline__ float hi2(u64 v){return __uint_as_float((unsigned)(v>>32));}
__device__ __forceinline__ float f2sum(u64 v){return lo2(v)+hi2(v);}
__device__ __forceinline__ float sigm(float v){return __fdividef(1.f,1.f+__expf(-v));}
__device__ __forceinline__ float tanhf_(float v){float e=__expf(2.f*v);return 1.f-__fdividef(2.f,e+1.f);}

__device__ __forceinline__ unsigned smaddr(const void* p){unsigned a;
    asm("{.reg .u64 t; cvta.to.shared.u64 t,%1; cvt.u32.u64 %0,t;}":"=r"(a):"l"(p));return a;}
__device__ __forceinline__ unsigned mapar(unsigned a,unsigned r){unsigned o;
    asm("mapa.shared::cluster.u32 %0,%1,%2;":"=r"(o):"r"(a),"r"(r));return o;}
__device__ __forceinline__ void stc64(unsigned a,u64 v){
    asm volatile("st.shared::cluster.b64 [%0],%1;"::"r"(a),"l"(v):"memory");}
__device__ __forceinline__ void cpa16(unsigned d,const void* s){
    asm volatile("cp.async.cg.shared.global [%0],[%1],16;"::"r"(d),"l"(s):"memory");}
#define CPCOMMIT() asm volatile("cp.async.commit_group;":::"memory")
#define CSYNC() do{asm volatile("barrier.cluster.arrive.aligned;":::"memory"); \
                   asm volatile("barrier.cluster.wait.aligned;":::"memory");}while(0)

__device__ __forceinline__ void split_st(__nv_bfloat16* base,size_t m,int col,float a,float b){
    __nv_bfloat16 ha=__float2bfloat16(a), hb=__float2bfloat16(b);
    __nv_bfloat16 la=__float2bfloat16(a-__bfloat162float(ha));
    __nv_bfloat16 lb=__float2bfloat16(b-__bfloat162float(hb));
    __nv_bfloat162 hi2v; hi2v.x=ha; hi2v.y=hb;
    __nv_bfloat162 lo2v; lo2v.x=la; lo2v.y=lb;
    *(__nv_bfloat162*)&base[m*1536+col]     =hi2v;
    *(__nv_bfloat162*)&base[m*1536+512+col] =lo2v;
    *(__nv_bfloat162*)&base[m*1536+1024+col]=hi2v;
}

// ===== layer 0 scan ========================================================
__global__ void __launch_bounds__(256,1) __cluster_dims__(4,1,1) gru0(
    const float* __restrict__ x,const float* __restrict__ Wih0,
    const float* __restrict__ Whh0,const float* __restrict__ bih0,
    const float* __restrict__ bhh0)
{
    extern __shared__ __align__(16) unsigned char smraw[];
    ulonglong2* wrz=(ulonglong2*)smraw;
    u64* wn=(u64*)(smraw+131072);
    float* hs=(float*)(smraw+196608);
    unsigned q; asm("mov.u32 %0,%%cluster_ctarank;":"=r"(q));
    const int cid=blockIdx.x>>2;
    const int dir=cid>>4, bbase=(cid&15)*16;
    const int tid=threadIdx.x, w=tid>>5, lane=tid&31;
    const int jp=(lane&7)|((w&3)<<3);
    const int sg=(lane>>3)|((w>>2)<<2);
    const int j0=q*64+2*jp, j1=j0+1;

    const float* Whh=Whh0+(size_t)dir*768*256;
    for(int i=tid;i<8192;i+=256){
        int k=i>>5,p=i&31,jj=q*64+2*p;
        ulonglong2 rz;
        rz.x=pk2(Whh[(size_t)(0*256+jj)*256+k],Whh[(size_t)(0*256+jj+1)*256+k]);
        rz.y=pk2(Whh[(size_t)(1*256+jj)*256+k],Whh[(size_t)(1*256+jj+1)*256+k]);
        wrz[i]=rz;
        wn[i]=pk2(Whh[(size_t)(2*256+jj)*256+k],Whh[(size_t)(2*256+jj+1)*256+k]);
    }
    const float* Wih=Wih0+(size_t)dir*768*4;
    const float4 wxr0=*(const float4*)&Wih[(0*256+j0)*4], wxr1=*(const float4*)&Wih[(0*256+j1)*4];
    const float4 wxz0=*(const float4*)&Wih[(1*256+j0)*4], wxz1=*(const float4*)&Wih[(1*256+j1)*4];
    const float4 wxn0=*(const float4*)&Wih[(2*256+j0)*4], wxn1=*(const float4*)&Wih[(2*256+j1)*4];
    const float* bi=bih0+dir*768; const float* bh=bhh0+dir*768;
    const float cr0=bi[j0],cr1=bi[j1],cz0=bi[256+j0],cz1=bi[256+j1],cn0=bi[512+j0],cn1=bi[512+j1];
    const float br0=bh[j0],br1=bh[j1],bz0=bh[256+j0],bz1=bh[256+j1],bn0=bh[512+j0],bn1=bh[512+j1];

    for(int i=tid;i<8192;i+=256)hs[i]=0.f;
    unsigned hsa=smaddr(hs);
    unsigned peer[4];
    #pragma unroll
    for(int r=0;r<4;r++)peer[r]=mapar(hsa,r);
    __syncthreads();
    CSYNC();

    const int s0=2*sg, s1=s0+1;
    const int bg0=bbase+s0, bg1=bbase+s1;

    for(int s=0;s<Tsz;s++){
        const int t=dir?255-s:s;
        const int cur=s&1;
        const u64* hk=(const u64*)(hs+cur*4096);
        u64 aR0=0,aZ0=0,aN0=0,aR1=0,aZ1=0,aN1=0;
        #pragma unroll 8
        for(int k=0;k<256;k++){
            u64 h2=hk[k*8+sg];
            u64 hA=dup2(lo2(h2)),hB=dup2(hi2(h2));
            ulonglong2 rz=wrz[k*32+jp];
            u64 nn=wn[k*32+jp];
            aR0=ffma2(hA,rz.x,aR0); aZ0=ffma2(hA,rz.y,aZ0); aN0=ffma2(hA,nn,aN0);
            aR1=ffma2(hB,rz.x,aR1); aZ1=ffma2(hB,rz.y,aZ1); aN1=ffma2(hB,nn,aN1);
        }
        float4 xv0=((const float4*)x)[(size_t)bg0*256+t];
        float4 xv1=((const float4*)x)[(size_t)bg1*256+t];
        const float* hc=hs+cur*4096;
        float hp00=hc[j0*16+s0],hp01=hc[j1*16+s0];
        float hp10=hc[j0*16+s1],hp11=hc[j1*16+s1];

        float xr0=cr0+xv0.x*wxr0.x+xv0.y*wxr0.y+xv0.z*wxr0.z+xv0.w*wxr0.w;
        float xr1=cr1+xv0.x*wxr1.x+xv0.y*wxr1.y+xv0.z*wxr1.z+xv0.w*wxr1.w;
        float xz0=cz0+xv0.x*wxz0.x+xv0.y*wxz0.y+xv0.z*wxz0.z+xv0.w*wxz0.w;
        float xz1=cz1+xv0.x*wxz1.x+xv0.y*wxz1.y+xv0.z*wxz1.z+xv0.w*wxz1.w;
        float xn0=cn0+xv0.x*wxn0.x+xv0.y*wxn0.y+xv0.z*wxn0.z+xv0.w*wxn0.w;
        float xn1=cn1+xv0.x*wxn1.x+xv0.y*wxn1.y+xv0.z*wxn1.z+xv0.w*wxn1.w;
        float r0=sigm(xr0+lo2(aR0)+br0), r1=sigm(xr1+hi2(aR0)+br1);
        float z0=sigm(xz0+lo2(aZ0)+bz0), z1=sigm(xz1+hi2(aZ0)+bz1);
        float n0=tanhf_(xn0+r0*(lo2(aN0)+bn0)), n1=tanhf_(xn1+r1*(hi2(aN0)+bn1));
        float hA0=(1.f-z0)*n0+z0*hp00, hA1=(1.f-z1)*n1+z1*hp01;

        xr0=cr0+xv1.x*wxr0.x+xv1.y*wxr0.y+xv1.z*wxr0.z+xv1.w*wxr0.w;
        xr1=cr1+xv1.x*wxr1.x+xv1.y*wxr1.y+xv1.z*wxr1.z+xv1.w*wxr1.w;
        xz0=cz0+xv1.x*wxz0.x+xv1.y*wxz0.y+xv1.z*wxz0.z+xv1.w*wxz0.w;
        xz1=cz1+xv1.x*wxz1.x+xv1.y*wxz1.y+xv1.z*wxz1.z+xv1.w*wxz1.w;
        xn0=cn0+xv1.x*wxn0.x+xv1.y*wxn0.y+xv1.z*wxn0.z+xv1.w*wxn0.w;
        xn1=cn1+xv1.x*wxn1.x+xv1.y*wxn1.y+xv1.z*wxn1.z+xv1.w*wxn1.w;
        r0=sigm(xr0+lo2(aR1)+br0); r1=sigm(xr1+hi2(aR1)+br1);
        z0=sigm(xz0+lo2(aZ1)+bz0); z1=sigm(xz1+hi2(aZ1)+bz1);
        n0=tanhf_(xn0+r0*(lo2(aN1)+bn0)); n1=tanhf_(xn1+r1*(hi2(aN1)+bn1));
        float hB0=(1.f-z0)*n0+z0*hp10, hB1=(1.f-z1)*n1+z1*hp11;

        const unsigned nxtb=(unsigned)((cur^1)*16384);
        u64 pj0=pk2(hA0,hB0), pj1=pk2(hA1,hB1);
        #pragma unroll
        for(int r=0;r<4;r++){
            unsigned pb=peer[r]+nxtb;
            stc64(pb+(unsigned)(j0*16+s0)*4,pj0);
            stc64(pb+(unsigned)(j1*16+s0)*4,pj1);
        }
        // emit bf16 hi/lo split directly (A' = [xh|xl|xh])
        split_st(g_ab,(size_t)bg0*256+t,dir*256+j0,hA0,hA1);
        split_st(g_ab,(size_t)bg1*256+t,dir*256+j0,hB0,hB1);
        if(t==255){
            *(float2*)&g_h1[(size_t)bg0*512+dir*256+j0]=make_float2(hA0,hA1);
            *(float2*)&g_h1[(size_t)bg1*512+dir*256+j0]=make_float2(hB0,hB1);
        }
        CSYNC();
    }
}

// ===== W conversion ========================================================
__global__ void convW(const float* __restrict__ Wih1){
    const int n=blockIdx.x, k=threadIdx.x;
    float w=Wih1[(size_t)n*512+k];
    __nv_bfloat16 hi=__float2bfloat16(w);
    __nv_bfloat16 lo=__float2bfloat16(w-__bfloat162float(hi));
    g_bb[(size_t)n*1536+k]=hi;
    g_bb[(size_t)n*1536+512+k]=hi;
    g_bb[(size_t)n*1536+1024+k]=lo;
}

// ===== xp GEMM via wmma bf16 + cp.async double buffering ===================
#define LDM 48
__global__ void __launch_bounds__(256,2) xpw(){
    __shared__ __nv_bfloat16 As[2][128][LDM], Bs[2][128][LDM];
    const int bn=blockIdx.x, bm=blockIdx.y;
    const int tid=threadIdx.x, wid=tid>>5;
    const int wm=wid>>1, wnb=wid&1;
    const int r=tid>>1, g=tid&1;      // 256 thr: 128 rows x 2 groups of 16B(8 bf16)... need 4 groups
    wmma::fragment<wmma::accumulator,16,16,16,float> acc[2][4];
    #pragma unroll
    for(int i=0;i<2;i++)
        #pragma unroll
        for(int j=0;j<4;j++)wmma::fill_fragment(acc[i][j],0.f);

    // per-stage load: 128 rows x 32 k = 512 x 8-bf16 groups; 256 thr -> 2 A + 2 B each
    const int lr=tid>>2, lg=tid&3;    // row 0..63(x2), group 0..3
    #define LOADST(st,kc) do{ \
        cpa16(smaddr(&As[st][lr][lg*8]),      &g_ab[(size_t)(bm*128+lr)*1536+(kc)*32+lg*8]); \
        cpa16(smaddr(&As[st][64+lr][lg*8]),   &g_ab[(size_t)(bm*128+64+lr)*1536+(kc)*32+lg*8]); \
        cpa16(smaddr(&Bs[st][lr][lg*8]),      &g_bb[(size_t)(bn*128+lr)*1536+(kc)*32+lg*8]); \
        cpa16(smaddr(&Bs[st][64+lr][lg*8]),   &g_bb[(size_t)(bn*128+64+lr)*1536+(kc)*32+lg*8]); \
        CPCOMMIT(); }while(0)

    LOADST(0,0);
    for(int kc=0;kc<48;kc++){
        const int st=kc&1;
        if(kc+1<48){
            LOADST(st^1,kc+1);
            asm volatile("cp.async.wait_group 1;":::"memory");
        }else{
            asm volatile("cp.async.wait_group 0;":::"memory");
        }
        __syncthreads();
        #pragma unroll
        for(int kk=0;kk<2;kk++){
            wmma::fragment<wmma::matrix_a,16,16,16,__nv_bfloat16,wmma::row_major> af[2];
            wmma::fragment<wmma::matrix_b,16,16,16,__nv_bfloat16,wmma::col_major> bf[4];
            #pragma unroll
            for(int i=0;i<2;i++)wmma::load_matrix_sync(af[i],&As[st][wm*32+i*16][kk*16],LDM);
            #pragma unroll
            for(int j=0;j<4;j++)wmma::load_matrix_sync(bf[j],&Bs[st][wnb*64+j*16][kk*16],LDM);
            #pragma unroll
            for(int i=0;i<2;i++)
                #pragma unroll
                for(int j=0;j<4;j++)wmma::mma_sync(acc[i][j],af[i],bf[j],acc[i][j]);
        }
        __syncthreads();
    }
    #pragma unroll
    for(int i=0;i<2;i++)
        #pragma unroll
        for(int j=0;j<4;j++)
            wmma::store_matrix_sync(&g_xp[(size_t)(bm*128+wm*32+i*16)*768+bn*128+wnb*64+j*16],
                                    acc[i][j],768,wmma::mem_row_major);
}

// ===== layer 1 fwd scan ====================================================
__global__ void __launch_bounds__(256,1) __cluster_dims__(4,1,1) gru1(
    const float* __restrict__ Whh1,const float* __restrict__ bih1,
    const float* __restrict__ bhh1)
{
    extern __shared__ __align__(16) unsigned char smraw[];
    ulonglong2* wrz=(ulonglong2*)smraw;
    u64* wn=(u64*)(smraw+131072);
    u64* hs2=(u64*)(smraw+196608);
    unsigned q; asm("mov.u32 %0,%%cluster_ctarank;":"=r"(q));
    const int cid=blockIdx.x>>2;
    const int tid=threadIdx.x, w=tid>>5, lane=tid&31;
    const int jp=(lane&7)|((w&3)<<3);
    const int sq=(lane>>3)|((w>>2)<<2);
    const int j0=q*64+2*jp, j1=j0+1;
    const int b=cid*8+sq;

    for(int i=tid;i<8192;i+=256){
        int k=i>>5,p=i&31,jj=q*64+2*p;
        ulonglong2 rz;
        rz.x=pk2(Whh1[(size_t)(0*256+jj)*256+k],Whh1[(size_t)(0*256+jj+1)*256+k]);
        rz.y=pk2(Whh1[(size_t)(1*256+jj)*256+k],Whh1[(size_t)(1*256+jj+1)*256+k]);
        wrz[i]=rz;
        wn[i]=pk2(Whh1[(size_t)(2*256+jj)*256+k],Whh1[(size_t)(2*256+jj+1)*256+k]);
    }
    const float cr0=bih1[j0]+bhh1[j0],         cr1=bih1[j1]+bhh1[j1];
    const float cz0=bih1[256+j0]+bhh1[256+j0], cz1=bih1[256+j1]+bhh1[256+j1];
    const float cx0=bih1[512+j0], cx1=bih1[512+j1];
    const float cn0=bhh1[512+j0], cn1=bhh1[512+j1];

    for(int i=tid;i<4096;i+=256)hs2[i]=0ull;
    unsigned hsa=smaddr(hs2);
    unsigned peer[4];
    #pragma unroll
    for(int r=0;r<4;r++)peer[r]=mapar(hsa,r);
    __syncthreads();
    CSYNC();

    for(int t=0;t<Tsz;t++){
        const int cur=t&1;
        const u64* hk=hs2+cur*2048;
        u64 aR=0,aZ=0,aN=0;
        #pragma unroll 8
        for(int k=0;k<256;k++){
            u64 hv=hk[k*8+sq];
            ulonglong2 rz=wrz[k*32+jp];
            aR=ffma2(hv,rz.x,aR); aZ=ffma2(hv,rz.y,aZ); aN=ffma2(hv,wn[k*32+jp],aN);
        }
        const float* xr_=&g_xp[(size_t)(b*256+t)*768];
        float2 pr=__ldg((const float2*)(xr_+j0));
        float2 pz=__ldg((const float2*)(xr_+256+j0));
        float2 pn=__ldg((const float2*)(xr_+512+j0));
        float hp0=lo2(hk[j0*8+sq]), hp1=lo2(hk[j1*8+sq]);
        float r0=sigm(pr.x+lo2(aR)+cr0), r1=sigm(pr.y+hi2(aR)+cr1);
        float z0=sigm(pz.x+lo2(aZ)+cz0), z1=sigm(pz.y+hi2(aZ)+cz1);
        float n0=tanhf_(pn.x+cx0+r0*(lo2(aN)+cn0));
        float n1=tanhf_(pn.y+cx1+r1*(hi2(aN)+cn1));
        float h0=(1.f-z0)*n0+z0*hp0, h1=(1.f-z1)*n1+z1*hp1;

        const unsigned nxtb=(unsigned)((cur^1)*16384);
        u64 s0=dup2(h0), s1=dup2(h1);
        #pragma unroll
        for(int r=0;r<4;r++){
            unsigned pb=peer[r]+nxtb;
            stc64(pb+(unsigned)(j0*8+sq)*8,s0);
            stc64(pb+(unsigned)(j1*8+sq)*8,s1);
        }
        if(t==255)*(float2*)&g_h2f[b*256+j0]=make_float2(h0,h1);
        CSYNC();
    }
}

// ===== layer 1 single bwd step (h=0) =======================================
__global__ void __launch_bounds__(256,1) g1bwd(
    const float* __restrict__ Wih1,const float* __restrict__ bih1,
    const float* __restrict__ bhh1)
{
    const int bt=blockIdx.x>>4, jt=blockIdx.x&15;
    const int tid=threadIdx.x, bl=tid>>3, jp=tid&7;
    const int b=bt*32+bl, j0=jt*16+2*jp, j1=j0+1;
    const float* W=Wih1+(size_t)768*512;
    const float2* xp=(const float2*)&g_h1[(size_t)b*512];
    const float2* wr0=(const float2*)&W[(size_t)(0*256+j0)*512];
    const float2* wr1=(const float2*)&W[(size_t)(0*256+j1)*512];
    const float2* wz0=(const float2*)&W[(size_t)(1*256+j0)*512];
    const float2* wz1=(const float2*)&W[(size_t)(1*256+j1)*512];
    const float2* wn0=(const float2*)&W[(size_t)(2*256+j0)*512];
    const float2* wn1=(const float2*)&W[(size_t)(2*256+j1)*512];
    u64 ar0=0,ar1=0,az0=0,az1=0,an0=0,an1=0;
    #pragma unroll 8
    for(int k2=0;k2<256;k2++){
        float2 xv=__ldg(&xp[k2]); u64 xu=pk2(xv.x,xv.y);
        float2 t0=__ldg(&wr0[k2]); ar0=ffma2(xu,pk2(t0.x,t0.y),ar0);
        float2 t1=__ldg(&wr1[k2]); ar1=ffma2(xu,pk2(t1.x,t1.y),ar1);
        float2 t2=__ldg(&wz0[k2]); az0=ffma2(xu,pk2(t2.x,t2.y),az0);
        float2 t3=__ldg(&wz1[k2]); az1=ffma2(xu,pk2(t3.x,t3.y),az1);
        float2 t4=__ldg(&wn0[k2]); an0=ffma2(xu,pk2(t4.x,t4.y),an0);
        float2 t5=__ldg(&wn1[k2]); an1=ffma2(xu,pk2(t5.x,t5.y),an1);
    }
    const float* bi=bih1+768; const float* bh=bhh1+768;
    float r0=sigm(f2sum(ar0)+bi[j0]+bh[j0]);
    float r1=sigm(f2sum(ar1)+bi[j1]+bh[j1]);
    float z0=sigm(f2sum(az0)+bi[256+j0]+bh[256+j0]);
    float z1=sigm(f2sum(az1)+bi[256+j1]+bh[256+j1]);
    float n0=tanhf_(f2sum(an0)+bi[512+j0]+r0*bh[512+j0]);
    float n1=tanhf_(f2sum(an1)+bi[512+j1]+r1*bh[512+j1]);
    *(float2*)&g_h2b[b*256+j0]=make_float2((1.f-z0)*n0,(1.f-z1)*n1);
}

// ===== head =====
__global__ void gru_head(const float* __restrict__ W_out,
                         const float* __restrict__ b_out,float* __restrict__ out){
    const int b=blockIdx.x, tid=threadIdx.x;
    float a0=0,a1=0,a2=0;
    for(int k=tid;k<Hsz;k+=128){
        float v=g_h2f[b*Hsz+k]+g_h2b[b*Hsz+k];
        a0+=v*W_out[k];a1+=v*W_out[256+k];a2+=v*W_out[512+k];
    }
    #pragma unroll
    for(int o=16;o>0;o>>=1){
        a0+=__shfl_xor_sync(0xffffffffu,a0,o);
        a1+=__shfl_xor_sync(0xffffffffu,a1,o);
        a2+=__shfl_xor_sync(0xffffffffu,a2,o);
    }
    __shared__ float red[3][4];
    if((tid&31)==0){int w=tid>>5;red[0][w]=a0;red[1][w]=a1;red[2][w]=a2;}
    __syncthreads();
    if(tid==0){
        a0=red[0][0]+red[0][1]+red[0][2]+red[0][3]+b_out[0];
        a1=red[1][0]+red[1][1]+red[1][2]+red[1][3]+b_out[1];
        a2=red[2][0]+red[2][1]+red[2][2]+red[2][3]+b_out[2];
        float m=fmaxf(a0,fmaxf(a1,a2));
        float e0=expf(a0-m),e1=expf(a1-m),e2=expf(a2-m);
        float inv=1.f/(e0+e1+e2);
        out[b*3+0]=e0*inv;out[b*3+1]=e1*inv;out[b*3+2]=e2*inv;
    }
}

extern "C" void kernel_launch(void* const* d_in,const int* in_sizes,int n_in,
                              void* d_out,int out_size){
    const float* x=(const float*)d_in[0];
    const float* Wih0=(const float*)d_in[1];
    const float* Whh0=(const float*)d_in[2];
    const float* bih0=(const float*)d_in[3];
    const float* bhh0=(const float*)d_in[4];
    const float* Wih1=(const float*)d_in[5];
    const float* Whh1=(const float*)d_in[6];
    const float* bih1=(const float*)d_in[7];
    const float* bhh1=(const float*)d_in[8];
    const float* W_out=(const float*)d_in[9];
    const float* b_out=(const float*)d_in[10];
    float* out=(float*)d_out;

    const int sm0=196608+32768;
    const int sm1=196608+32768;
    cudaFuncSetAttribute(gru0,cudaFuncAttributeMaxDynamicSharedMemorySize,sm0);
    cudaFuncSetAttribute(gru1,cudaFuncAttributeMaxDynamicSharedMemorySize,sm1);

    convW<<<768,512>>>(Wih1);
    gru0<<<128,256,sm0>>>(x,Wih0,Whh0,bih0,bhh0);
    xpw<<<dim3(6,512),256>>>();
    g1bwd<<<128,256>>>(Wih1,bih1,bhh1);
    gru1<<<128,256,sm1>>>(Whh1,bih1,bhh1);
    gru_head<<<256,128>>>(W_out,b_out,out);
}

// round 14
// speedup vs baseline: 1.9402x; 1.0155x over previous
#include <cuda_runtime.h>
#include <cuda_bf16.h>
#include <mma.h>
#include <math.h>
using namespace nvcuda;

#define Tsz 256
#define Hsz 256

__device__ float g_h1[(size_t)256*512];             // only t=255 rows [b][512]
__device__ float g_xp[(size_t)65536*768];
__device__ float g_h2f[256*256];
__device__ float g_h2b[256*256];
__device__ __nv_bfloat16 g_ab[(size_t)65536*1536];  // A' = [xh|xl|xh]
__device__ __nv_bfloat16 g_bb[(size_t)768*1536];    // B' = [Wh|Wh|Wl]

typedef unsigned long long u64;
__device__ __forceinline__ u64 ffma2(u64 a,u64 b,u64 c){u64 d;asm("fma.rn.f32x2 %0,%1,%2,%3;":"=l"(d):"l"(a),"l"(b),"l"(c));return d;}
__device__ __forceinline__ u64 dup2(float v){u64 d;asm("mov.b64 %0,{%1,%2};":"=l"(d):"f"(v),"f"(v));return d;}
__device__ __forceinline__ u64 pk2(float a,float b){u64 d;asm("mov.b64 %0,{%1,%2};":"=l"(d):"f"(a),"f"(b));return d;}
__device__ __forceinline__ float lo2(u64 v){return __uint_as_float((unsigned)v);}
__device__ __forceinline__ float hi2(u64 v){return __uint_as_float((unsigned)(v>>32));}
__device__ __forceinline__ float f2sum(u64 v){return lo2(v)+hi2(v);}
__device__ __forceinline__ float sigm(float v){return __fdividef(1.f,1.f+__expf(-v));}
__device__ __forceinline__ float tanhf_(float v){float e=__expf(2.f*v);return 1.f-__fdividef(2.f,e+1.f);}

__device__ __forceinline__ unsigned smaddr(const void* p){unsigned a;
    asm("{.reg .u64 t; cvta.to.shared.u64 t,%1; cvt.u32.u64 %0,t;}":"=r"(a):"l"(p));return a;}
__device__ __forceinline__ unsigned mapar(unsigned a,unsigned r){unsigned o;
    asm("mapa.shared::cluster.u32 %0,%1,%2;":"=r"(o):"r"(a),"r"(r));return o;}
__device__ __forceinline__ void stc64(unsigned a,u64 v){
    asm volatile("st.shared::cluster.b64 [%0],%1;"::"r"(a),"l"(v):"memory");}
__device__ __forceinline__ void cpa16(unsigned d,const void* s){
    asm volatile("cp.async.cg.shared.global [%0],[%1],16;"::"r"(d),"l"(s):"memory");}
#define CPCOMMIT() asm volatile("cp.async.commit_group;":::"memory")
#define CSYNC() do{asm volatile("barrier.cluster.arrive.aligned;":::"memory"); \
                   asm volatile("barrier.cluster.wait.aligned;":::"memory");}while(0)

__device__ __forceinline__ void split_st(__nv_bfloat16* base,size_t m,int col,float a,float b){
    __nv_bfloat16 ha=__float2bfloat16(a), hb=__float2bfloat16(b);
    __nv_bfloat16 la=__float2bfloat16(a-__bfloat162float(ha));
    __nv_bfloat16 lb=__float2bfloat16(b-__bfloat162float(hb));
    __nv_bfloat162 hi2v; hi2v.x=ha; hi2v.y=hb;
    __nv_bfloat162 lo2v; lo2v.x=la; lo2v.y=lb;
    *(__nv_bfloat162*)&base[m*1536+col]     =hi2v;
    *(__nv_bfloat162*)&base[m*1536+512+col] =lo2v;
    *(__nv_bfloat162*)&base[m*1536+1024+col]=hi2v;
}

// ===== layer 0 scan ========================================================
__global__ void __launch_bounds__(256,1) __cluster_dims__(4,1,1) gru0(
    const float* __restrict__ x,const float* __restrict__ Wih0,
    const float* __restrict__ Whh0,const float* __restrict__ bih0,
    const float* __restrict__ bhh0)
{
    extern __shared__ __align__(16) unsigned char smraw[];
    ulonglong2* wrz=(ulonglong2*)smraw;
    u64* wn=(u64*)(smraw+131072);
    float* hs=(float*)(smraw+196608);
    unsigned q; asm("mov.u32 %0,%%cluster_ctarank;":"=r"(q));
    const int cid=blockIdx.x>>2;
    const int dir=cid>>4, bbase=(cid&15)*16;
    const int tid=threadIdx.x, w=tid>>5, lane=tid&31;
    const int jp=(lane&7)|((w&3)<<3);
    const int sg=(lane>>3)|((w>>2)<<2);
    const int j0=q*64+2*jp, j1=j0+1;

    const float* Whh=Whh0+(size_t)dir*768*256;
    for(int i=tid;i<8192;i+=256){
        int k=i>>5,p=i&31,jj=q*64+2*p;
        ulonglong2 rz;
        rz.x=pk2(Whh[(size_t)(0*256+jj)*256+k],Whh[(size_t)(0*256+jj+1)*256+k]);
        rz.y=pk2(Whh[(size_t)(1*256+jj)*256+k],Whh[(size_t)(1*256+jj+1)*256+k]);
        wrz[i]=rz;
        wn[i]=pk2(Whh[(size_t)(2*256+jj)*256+k],Whh[(size_t)(2*256+jj+1)*256+k]);
    }
    const float* Wih=Wih0+(size_t)dir*768*4;
    const float4 wxr0=*(const float4*)&Wih[(0*256+j0)*4], wxr1=*(const float4*)&Wih[(0*256+j1)*4];
    const float4 wxz0=*(const float4*)&Wih[(1*256+j0)*4], wxz1=*(const float4*)&Wih[(1*256+j1)*4];
    const float4 wxn0=*(const float4*)&Wih[(2*256+j0)*4], wxn1=*(const float4*)&Wih[(2*256+j1)*4];
    const float* bi=bih0+dir*768; const float* bh=bhh0+dir*768;
    const float cr0=bi[j0],cr1=bi[j1],cz0=bi[256+j0],cz1=bi[256+j1],cn0=bi[512+j0],cn1=bi[512+j1];
    const float br0=bh[j0],br1=bh[j1],bz0=bh[256+j0],bz1=bh[256+j1],bn0=bh[512+j0],bn1=bh[512+j1];

    for(int i=tid;i<8192;i+=256)hs[i]=0.f;
    unsigned hsa=smaddr(hs);
    unsigned peer[4];
    #pragma unroll
    for(int r=0;r<4;r++)peer[r]=mapar(hsa,r);
    __syncthreads();
    CSYNC();

    const int s0=2*sg, s1=s0+1;
    const int bg0=bbase+s0, bg1=bbase+s1;

    for(int s=0;s<Tsz;s++){
        const int t=dir?255-s:s;
        const int cur=s&1;
        const u64* hk=(const u64*)(hs+cur*4096);
        u64 aR0=0,aZ0=0,aN0=0,aR1=0,aZ1=0,aN1=0;
        #pragma unroll 8
        for(int k=0;k<256;k++){
            u64 h2=hk[k*8+sg];
            u64 hA=dup2(lo2(h2)),hB=dup2(hi2(h2));
            ulonglong2 rz=wrz[k*32+jp];
            u64 nn=wn[k*32+jp];
            aR0=ffma2(hA,rz.x,aR0); aZ0=ffma2(hA,rz.y,aZ0); aN0=ffma2(hA,nn,aN0);
            aR1=ffma2(hB,rz.x,aR1); aZ1=ffma2(hB,rz.y,aZ1); aN1=ffma2(hB,nn,aN1);
        }
        float4 xv0=((const float4*)x)[(size_t)bg0*256+t];
        float4 xv1=((const float4*)x)[(size_t)bg1*256+t];
        const float* hc=hs+cur*4096;
        float hp00=hc[j0*16+s0],hp01=hc[j1*16+s0];
        float hp10=hc[j0*16+s1],hp11=hc[j1*16+s1];

        float xr0=cr0+xv0.x*wxr0.x+xv0.y*wxr0.y+xv0.z*wxr0.z+xv0.w*wxr0.w;
        float xr1=cr1+xv0.x*wxr1.x+xv0.y*wxr1.y+xv0.z*wxr1.z+xv0.w*wxr1.w;
        float xz0=cz0+xv0.x*wxz0.x+xv0.y*wxz0.y+xv0.z*wxz0.z+xv0.w*wxz0.w;
        float xz1=cz1+xv0.x*wxz1.x+xv0.y*wxz1.y+xv0.z*wxz1.z+xv0.w*wxz1.w;
        float xn0=cn0+xv0.x*wxn0.x+xv0.y*wxn0.y+xv0.z*wxn0.z+xv0.w*wxn0.w;
        float xn1=cn1+xv0.x*wxn1.x+xv0.y*wxn1.y+xv0.z*wxn1.z+xv0.w*wxn1.w;
        float r0=sigm(xr0+lo2(aR0)+br0), r1=sigm(xr1+hi2(aR0)+br1);
        float z0=sigm(xz0+lo2(aZ0)+bz0), z1=sigm(xz1+hi2(aZ0)+bz1);
        float n0=tanhf_(xn0+r0*(lo2(aN0)+bn0)), n1=tanhf_(xn1+r1*(hi2(aN0)+bn1));
        float hA0=(1.f-z0)*n0+z0*hp00, hA1=(1.f-z1)*n1+z1*hp01;

        xr0=cr0+xv1.x*wxr0.x+xv1.y*wxr0.y+xv1.z*wxr0.z+xv1.w*wxr0.w;
        xr1=cr1+xv1.x*wxr1.x+xv1.y*wxr1.y+xv1.z*wxr1.z+xv1.w*wxr1.w;
        xz0=cz0+xv1.x*wxz0.x+xv1.y*wxz0.y+xv1.z*wxz0.z+xv1.w*wxz0.w;
        xz1=cz1+xv1.x*wxz1.x+xv1.y*wxz1.y+xv1.z*wxz1.z+xv1.w*wxz1.w;
        xn0=cn0+xv1.x*wxn0.x+xv1.y*wxn0.y+xv1.z*wxn0.z+xv1.w*wxn0.w;
        xn1=cn1+xv1.x*wxn1.x+xv1.y*wxn1.y+xv1.z*wxn1.z+xv1.w*wxn1.w;
        r0=sigm(xr0+lo2(aR1)+br0); r1=sigm(xr1+hi2(aR1)+br1);
        z0=sigm(xz0+lo2(aZ1)+bz0); z1=sigm(xz1+hi2(aZ1)+bz1);
        n0=tanhf_(xn0+r0*(lo2(aN1)+bn0)); n1=tanhf_(xn1+r1*(hi2(aN1)+bn1));
        float hB0=(1.f-z0)*n0+z0*hp10, hB1=(1.f-z1)*n1+z1*hp11;

        const unsigned nxtb=(unsigned)((cur^1)*16384);
        u64 pj0=pk2(hA0,hB0), pj1=pk2(hA1,hB1);
        #pragma unroll
        for(int r=0;r<4;r++){
            unsigned pb=peer[r]+nxtb;
            stc64(pb+(unsigned)(j0*16+s0)*4,pj0);
            stc64(pb+(unsigned)(j1*16+s0)*4,pj1);
        }
        split_st(g_ab,(size_t)bg0*256+t,dir*256+j0,hA0,hA1);
        split_st(g_ab,(size_t)bg1*256+t,dir*256+j0,hB0,hB1);
        if(t==255){
            *(float2*)&g_h1[(size_t)bg0*512+dir*256+j0]=make_float2(hA0,hA1);
            *(float2*)&g_h1[(size_t)bg1*512+dir*256+j0]=make_float2(hB0,hB1);
        }
        CSYNC();
    }
}

// ===== W conversion ========================================================
__global__ void convW(const float* __restrict__ Wih1){
    const int n=blockIdx.x, k=threadIdx.x;
    float w=Wih1[(size_t)n*512+k];
    __nv_bfloat16 hi=__float2bfloat16(w);
    __nv_bfloat16 lo=__float2bfloat16(w-__bfloat162float(hi));
    g_bb[(size_t)n*1536+k]=hi;
    g_bb[(size_t)n*1536+512+k]=hi;
    g_bb[(size_t)n*1536+1024+k]=lo;
}

// ===== xp GEMM via wmma bf16 + 3-stage cp.async pipeline ===================
#define LDM 48
__global__ void __launch_bounds__(256,2) xpw(){
    __shared__ __nv_bfloat16 As[3][128][LDM], Bs[3][128][LDM];
    const int bn=blockIdx.x, bm=blockIdx.y;
    const int tid=threadIdx.x, wid=tid>>5;
    const int wm=wid>>1, wnb=wid&1;
    wmma::fragment<wmma::accumulator,16,16,16,float> acc[2][4];
    #pragma unroll
    for(int i=0;i<2;i++)
        #pragma unroll
        for(int j=0;j<4;j++)wmma::fill_fragment(acc[i][j],0.f);

    const int lr=tid>>2, lg=tid&3;
    #define LOADST(st,kc) do{ \
        cpa16(smaddr(&As[st][lr][lg*8]),      &g_ab[(size_t)(bm*128+lr)*1536+(kc)*32+lg*8]); \
        cpa16(smaddr(&As[st][64+lr][lg*8]),   &g_ab[(size_t)(bm*128+64+lr)*1536+(kc)*32+lg*8]); \
        cpa16(smaddr(&Bs[st][lr][lg*8]),      &g_bb[(size_t)(bn*128+lr)*1536+(kc)*32+lg*8]); \
        cpa16(smaddr(&Bs[st][64+lr][lg*8]),   &g_bb[(size_t)(bn*128+64+lr)*1536+(kc)*32+lg*8]); \
        CPCOMMIT(); }while(0)

    LOADST(0,0); LOADST(1,1);
    for(int kc=0;kc<48;kc++){
        const int st=kc%3;
        if(kc<46){
            LOADST((kc+2)%3,kc+2);
            asm volatile("cp.async.wait_group 2;":::"memory");
        }else if(kc==46){
            asm volatile("cp.async.wait_group 1;":::"memory");
        }else{
            asm volatile("cp.async.wait_group 0;":::"memory");
        }
        __syncthreads();
        #pragma unroll
        for(int kk=0;kk<2;kk++){
            wmma::fragment<wmma::matrix_a,16,16,16,__nv_bfloat16,wmma::row_major> af[2];
            wmma::fragment<wmma::matrix_b,16,16,16,__nv_bfloat16,wmma::col_major> bf[4];
            #pragma unroll
            for(int i=0;i<2;i++)wmma::load_matrix_sync(af[i],&As[st][wm*32+i*16][kk*16],LDM);
            #pragma unroll
            for(int j=0;j<4;j++)wmma::load_matrix_sync(bf[j],&Bs[st][wnb*64+j*16][kk*16],LDM);
            #pragma unroll
            for(int i=0;i<2;i++)
                #pragma unroll
                for(int j=0;j<4;j++)wmma::mma_sync(acc[i][j],af[i],bf[j],acc[i][j]);
        }
        __syncthreads();
    }
    #pragma unroll
    for(int i=0;i<2;i++)
        #pragma unroll
        for(int j=0;j<4;j++)
            wmma::store_matrix_sync(&g_xp[(size_t)(bm*128+wm*32+i*16)*768+bn*128+wnb*64+j*16],
                                    acc[i][j],768,wmma::mem_row_major);
}

// ===== layer 1 fwd scan ====================================================
__global__ void __launch_bounds__(256,1) __cluster_dims__(4,1,1) gru1(
    const float* __restrict__ Whh1,const float* __restrict__ bih1,
    const float* __restrict__ bhh1)
{
    extern __shared__ __align__(16) unsigned char smraw[];
    ulonglong2* wrz=(ulonglong2*)smraw;
    u64* wn=(u64*)(smraw+131072);
    u64* hs2=(u64*)(smraw+196608);
    unsigned q; asm("mov.u32 %0,%%cluster_ctarank;":"=r"(q));
    const int cid=blockIdx.x>>2;
    const int tid=threadIdx.x, w=tid>>5, lane=tid&31;
    const int jp=(lane&7)|((w&3)<<3);
    const int sq=(lane>>3)|((w>>2)<<2);
    const int j0=q*64+2*jp, j1=j0+1;
    const int b=cid*8+sq;

    for(int i=tid;i<8192;i+=256){
        int k=i>>5,p=i&31,jj=q*64+2*p;
        ulonglong2 rz;
        rz.x=pk2(Whh1[(size_t)(0*256+jj)*256+k],Whh1[(size_t)(0*256+jj+1)*256+k]);
        rz.y=pk2(Whh1[(size_t)(1*256+jj)*256+k],Whh1[(size_t)(1*256+jj+1)*256+k]);
        wrz[i]=rz;
        wn[i]=pk2(Whh1[(size_t)(2*256+jj)*256+k],Whh1[(size_t)(2*256+jj+1)*256+k]);
    }
    const float cr0=bih1[j0]+bhh1[j0],         cr1=bih1[j1]+bhh1[j1];
    const float cz0=bih1[256+j0]+bhh1[256+j0], cz1=bih1[256+j1]+bhh1[256+j1];
    const float cx0=bih1[512+j0], cx1=bih1[512+j1];
    const float cn0=bhh1[512+j0], cn1=bhh1[512+j1];

    for(int i=tid;i<4096;i+=256)hs2[i]=0ull;
    unsigned hsa=smaddr(hs2);
    unsigned peer[4];
    #pragma unroll
    for(int r=0;r<4;r++)peer[r]=mapar(hsa,r);
    __syncthreads();
    CSYNC();

    for(int t=0;t<Tsz;t++){
        const int cur=t&1;
        const u64* hk=hs2+cur*2048;
        u64 aR=0,aZ=0,aN=0;
        #pragma unroll 8
        for(int k=0;k<256;k++){
            u64 hv=hk[k*8+sq];
            ulonglong2 rz=wrz[k*32+jp];
            aR=ffma2(hv,rz.x,aR); aZ=ffma2(hv,rz.y,aZ); aN=ffma2(hv,wn[k*32+jp],aN);
        }
        const float* xr_=&g_xp[(size_t)(b*256+t)*768];
        float2 pr=__ldg((const float2*)(xr_+j0));
        float2 pz=__ldg((const float2*)(xr_+256+j0));
        float2 pn=__ldg((const float2*)(xr_+512+j0));
        float hp0=lo2(hk[j0*8+sq]), hp1=lo2(hk[j1*8+sq]);
        float r0=sigm(pr.x+lo2(aR)+cr0), r1=sigm(pr.y+hi2(aR)+cr1);
        float z0=sigm(pz.x+lo2(aZ)+cz0), z1=sigm(pz.y+hi2(aZ)+cz1);
        float n0=tanhf_(pn.x+cx0+r0*(lo2(aN)+cn0));
        float n1=tanhf_(pn.y+cx1+r1*(hi2(aN)+cn1));
        float h0=(1.f-z0)*n0+z0*hp0, h1=(1.f-z1)*n1+z1*hp1;

        const unsigned nxtb=(unsigned)((cur^1)*16384);
        u64 s0=dup2(h0), s1=dup2(h1);
        #pragma unroll
        for(int r=0;r<4;r++){
            unsigned pb=peer[r]+nxtb;
            stc64(pb+(unsigned)(j0*8+sq)*8,s0);
            stc64(pb+(unsigned)(j1*8+sq)*8,s1);
        }
        if(t==255)*(float2*)&g_h2f[b*256+j0]=make_float2(h0,h1);
        CSYNC();
    }
}

// ===== layer 1 single bwd step (h=0): smem-staged weights ==================
__global__ void __launch_bounds__(256,1) g1bwd(
    const float* __restrict__ Wih1,const float* __restrict__ bih1,
    const float* __restrict__ bhh1)
{
    extern __shared__ __align__(16) u64 ws[];   // [3][512][8 jp] = 98,304 B
    const int bt=blockIdx.x>>4, jt=blockIdx.x&15;
    const int tid=threadIdx.x;
    const float* W=Wih1+(size_t)768*512;

    for(int i=tid;i<3*512*8;i+=256){
        int p=i&7, k=(i>>3)&511, g=i>>12;
        int J0=jt*16+2*p;
        ws[i]=pk2(W[(size_t)(g*256+J0)*512+k],W[(size_t)(g*256+J0+1)*512+k]);
    }
    __syncthreads();

    const int bl=tid>>3, jp=tid&7;
    const int b=bt*32+bl, j0=jt*16+2*jp, j1=j0+1;
    const float2* xp=(const float2*)&g_h1[(size_t)b*512];
    u64 ar=0,az=0,an=0;
    #pragma unroll 8
    for(int k2=0;k2<256;k2++){
        float2 xv=__ldg(&xp[k2]);
        u64 x0=dup2(xv.x),x1=dup2(xv.y);
        ar=ffma2(x0,ws[(size_t)(0*512+2*k2  )*8+jp],ar);
        ar=ffma2(x1,ws[(size_t)(0*512+2*k2+1)*8+jp],ar);
        az=ffma2(x0,ws[(size_t)(1*512+2*k2  )*8+jp],az);
        az=ffma2(x1,ws[(size_t)(1*512+2*k2+1)*8+jp],az);
        an=ffma2(x0,ws[(size_t)(2*512+2*k2  )*8+jp],an);
        an=ffma2(x1,ws[(size_t)(2*512+2*k2+1)*8+jp],an);
    }
    const float* bi=bih1+768; const float* bh=bhh1+768;
    float r0=sigm(lo2(ar)+bi[j0]+bh[j0]);
    float r1=sigm(hi2(ar)+bi[j1]+bh[j1]);
    float z0=sigm(lo2(az)+bi[256+j0]+bh[256+j0]);
    float z1=sigm(hi2(az)+bi[256+j1]+bh[256+j1]);
    float n0=tanhf_(lo2(an)+bi[512+j0]+r0*bh[512+j0]);
    float n1=tanhf_(hi2(an)+bi[512+j1]+r1*bh[512+j1]);
    *(float2*)&g_h2b[b*256+j0]=make_float2((1.f-z0)*n0,(1.f-z1)*n1);
}

// ===== head =====
__global__ void gru_head(const float* __restrict__ W_out,
                         const float* __restrict__ b_out,float* __restrict__ out){
    const int b=blockIdx.x, tid=threadIdx.x;
    float a0=0,a1=0,a2=0;
    for(int k=tid;k<Hsz;k+=128){
        float v=g_h2f[b*Hsz+k]+g_h2b[b*Hsz+k];
        a0+=v*W_out[k];a1+=v*W_out[256+k];a2+=v*W_out[512+k];
    }
    #pragma unroll
    for(int o=16;o>0;o>>=1){
        a0+=__shfl_xor_sync(0xffffffffu,a0,o);
        a1+=__shfl_xor_sync(0xffffffffu,a1,o);
        a2+=__shfl_xor_sync(0xffffffffu,a2,o);
    }
    __shared__ float red[3][4];
    if((tid&31)==0){int w=tid>>5;red[0][w]=a0;red[1][w]=a1;red[2][w]=a2;}
    __syncthreads();
    if(tid==0){
        a0=red[0][0]+red[0][1]+red[0][2]+red[0][3]+b_out[0];
        a1=red[1][0]+red[1][1]+red[1][2]+red[1][3]+b_out[1];
        a2=red[2][0]+red[2][1]+red[2][2]+red[2][3]+b_out[2];
        float m=fmaxf(a0,fmaxf(a1,a2));
        float e0=expf(a0-m),e1=expf(a1-m),e2=expf(a2-m);
        float inv=1.f/(e0+e1+e2);
        out[b*3+0]=e0*inv;out[b*3+1]=e1*inv;out[b*3+2]=e2*inv;
    }
}

extern "C" void kernel_launch(void* const* d_in,const int* in_sizes,int n_in,
                              void* d_out,int out_size){
    const float* x=(const float*)d_in[0];
    const float* Wih0=(const float*)d_in[1];
    const float* Whh0=(const float*)d_in[2];
    const float* bih0=(const float*)d_in[3];
    const float* bhh0=(const float*)d_in[4];
    const float* Wih1=(const float*)d_in[5];
    const float* Whh1=(const float*)d_in[6];
    const float* bih1=(const float*)d_in[7];
    const float* bhh1=(const float*)d_in[8];
    const float* W_out=(const float*)d_in[9];
    const float* b_out=(const float*)d_in[10];
    float* out=(float*)d_out;

    const int sm0=196608+32768;
    const int sm1=196608+32768;
    const int smb=98304;
    cudaFuncSetAttribute(gru0,cudaFuncAttributeMaxDynamicSharedMemorySize,sm0);
    cudaFuncSetAttribute(gru1,cudaFuncAttributeMaxDynamicSharedMemorySize,sm1);
    cudaFuncSetAttribute(g1bwd,cudaFuncAttributeMaxDynamicSharedMemorySize,smb);

    convW<<<768,512>>>(Wih1);
    gru0<<<128,256,sm0>>>(x,Wih0,Whh0,bih0,bhh0);
    xpw<<<dim3(6,512),256>>>();
    g1bwd<<<128,256,smb>>>(Wih1,bih1,bhh1);
    gru1<<<128,256,sm1>>>(Whh1,bih1,bhh1);
    gru_head<<<256,128>>>(W_out,b_out,out);
}

// round 15
// speedup vs baseline: 2.0132x; 1.0376x over previous
#include <cuda_runtime.h>
#include <cuda_bf16.h>
#include <mma.h>
#include <math.h>
using namespace nvcuda;

#define Tsz 256
#define Hsz 256

__device__ float g_h1[(size_t)256*512];             // only t=255 rows [b][512]
__device__ float g_xp[(size_t)65536*768];
__device__ float g_h2f[256*256];
__device__ float g_h2b[256*256];
__device__ __nv_bfloat16 g_ab[(size_t)65536*1536];  // A' = [xh|xl|xh]
__device__ __nv_bfloat16 g_bb[(size_t)768*1536];    // B' = [Wh|Wh|Wl]

typedef unsigned long long u64;
__device__ __forceinline__ u64 ffma2(u64 a,u64 b,u64 c){u64 d;asm("fma.rn.f32x2 %0,%1,%2,%3;":"=l"(d):"l"(a),"l"(b),"l"(c));return d;}
__device__ __forceinline__ u64 dup2(float v){u64 d;asm("mov.b64 %0,{%1,%2};":"=l"(d):"f"(v),"f"(v));return d;}
__device__ __forceinline__ u64 pk2(float a,float b){u64 d;asm("mov.b64 %0,{%1,%2};":"=l"(d):"f"(a),"f"(b));return d;}
__device__ __forceinline__ float lo2(u64 v){return __uint_as_float((unsigned)v);}
__device__ __forceinline__ float hi2(u64 v){return __uint_as_float((unsigned)(v>>32));}
__device__ __forceinline__ float f2sum(u64 v){return lo2(v)+hi2(v);}
__device__ __forceinline__ float sigm(float v){return __fdividef(1.f,1.f+__expf(-v));}
__device__ __forceinline__ float tanhf_(float v){float e=__expf(2.f*v);return 1.f-__fdividef(2.f,e+1.f);}

__device__ __forceinline__ unsigned smaddr(const void* p){unsigned a;
    asm("{.reg .u64 t; cvta.to.shared.u64 t,%1; cvt.u32.u64 %0,t;}":"=r"(a):"l"(p));return a;}
__device__ __forceinline__ unsigned mapar(unsigned a,unsigned r){unsigned o;
    asm("mapa.shared::cluster.u32 %0,%1,%2;":"=r"(o):"r"(a),"r"(r));return o;}
__device__ __forceinline__ void stc64(unsigned a,u64 v){
    asm volatile("st.shared::cluster.b64 [%0],%1;"::"r"(a),"l"(v):"memory");}
__device__ __forceinline__ void cpa16(unsigned d,const void* s){
    asm volatile("cp.async.cg.shared.global [%0],[%1],16;"::"r"(d),"l"(s):"memory");}
#define CPCOMMIT() asm volatile("cp.async.commit_group;":::"memory")
#define CARRIVE() asm volatile("barrier.cluster.arrive.aligned;":::"memory")
#define CWAIT()   asm volatile("barrier.cluster.wait.aligned;":::"memory")
#define CSYNC()   do{CARRIVE();CWAIT();}while(0)

__device__ __forceinline__ void split_st(__nv_bfloat16* base,size_t m,int col,float a,float b){
    __nv_bfloat16 ha=__float2bfloat16(a), hb=__float2bfloat16(b);
    __nv_bfloat16 la=__float2bfloat16(a-__bfloat162float(ha));
    __nv_bfloat16 lb=__float2bfloat16(b-__bfloat162float(hb));
    __nv_bfloat162 hi2v; hi2v.x=ha; hi2v.y=hb;
    __nv_bfloat162 lo2v; lo2v.x=la; lo2v.y=lb;
    *(__nv_bfloat162*)&base[m*1536+col]     =hi2v;
    *(__nv_bfloat162*)&base[m*1536+512+col] =lo2v;
    *(__nv_bfloat162*)&base[m*1536+1024+col]=hi2v;
}

// ===== layer 0 scan: split arrive/wait, globals hidden behind barrier ======
__global__ void __launch_bounds__(256,1) __cluster_dims__(4,1,1) gru0(
    const float* __restrict__ x,const float* __restrict__ Wih0,
    const float* __restrict__ Whh0,const float* __restrict__ bih0,
    const float* __restrict__ bhh0)
{
    extern __shared__ __align__(16) unsigned char smraw[];
    ulonglong2* wrz=(ulonglong2*)smraw;
    u64* wn=(u64*)(smraw+131072);
    float* hs=(float*)(smraw+196608);
    unsigned q; asm("mov.u32 %0,%%cluster_ctarank;":"=r"(q));
    const int cid=blockIdx.x>>2;
    const int dir=cid>>4, bbase=(cid&15)*16;
    const int tid=threadIdx.x, w=tid>>5, lane=tid&31;
    const int jp=(lane&7)|((w&3)<<3);
    const int sg=(lane>>3)|((w>>2)<<2);
    const int j0=q*64+2*jp, j1=j0+1;

    const float* Whh=Whh0+(size_t)dir*768*256;
    for(int i=tid;i<8192;i+=256){
        int k=i>>5,p=i&31,jj=q*64+2*p;
        ulonglong2 rz;
        rz.x=pk2(Whh[(size_t)(0*256+jj)*256+k],Whh[(size_t)(0*256+jj+1)*256+k]);
        rz.y=pk2(Whh[(size_t)(1*256+jj)*256+k],Whh[(size_t)(1*256+jj+1)*256+k]);
        wrz[i]=rz;
        wn[i]=pk2(Whh[(size_t)(2*256+jj)*256+k],Whh[(size_t)(2*256+jj+1)*256+k]);
    }
    const float* Wih=Wih0+(size_t)dir*768*4;
    const float4 wxr0=*(const float4*)&Wih[(0*256+j0)*4], wxr1=*(const float4*)&Wih[(0*256+j1)*4];
    const float4 wxz0=*(const float4*)&Wih[(1*256+j0)*4], wxz1=*(const float4*)&Wih[(1*256+j1)*4];
    const float4 wxn0=*(const float4*)&Wih[(2*256+j0)*4], wxn1=*(const float4*)&Wih[(2*256+j1)*4];
    const float* bi=bih0+dir*768; const float* bh=bhh0+dir*768;
    const float cr0=bi[j0],cr1=bi[j1],cz0=bi[256+j0],cz1=bi[256+j1],cn0=bi[512+j0],cn1=bi[512+j1];
    const float br0=bh[j0],br1=bh[j1],bz0=bh[256+j0],bz1=bh[256+j1],bn0=bh[512+j0],bn1=bh[512+j1];

    for(int i=tid;i<8192;i+=256)hs[i]=0.f;
    unsigned hsa=smaddr(hs);
    unsigned peer[4];
    #pragma unroll
    for(int r=0;r<4;r++)peer[r]=mapar(hsa,r);
    __syncthreads();
    CSYNC();

    const int s0=2*sg, s1=s0+1;
    const int bg0=bbase+s0, bg1=bbase+s1;

    for(int s=0;s<Tsz;s++){
        const int t=dir?255-s:s;
        const int cur=s&1;
        const u64* hk=(const u64*)(hs+cur*4096);
        u64 aR0=0,aZ0=0,aN0=0,aR1=0,aZ1=0,aN1=0;
        #pragma unroll 8
        for(int k=0;k<256;k++){
            u64 h2=hk[k*8+sg];
            u64 hA=dup2(lo2(h2)),hB=dup2(hi2(h2));
            ulonglong2 rz=wrz[k*32+jp];
            u64 nn=wn[k*32+jp];
            aR0=ffma2(hA,rz.x,aR0); aZ0=ffma2(hA,rz.y,aZ0); aN0=ffma2(hA,nn,aN0);
            aR1=ffma2(hB,rz.x,aR1); aZ1=ffma2(hB,rz.y,aZ1); aN1=ffma2(hB,nn,aN1);
        }
        float4 xv0=((const float4*)x)[(size_t)bg0*256+t];
        float4 xv1=((const float4*)x)[(size_t)bg1*256+t];
        const float* hc=hs+cur*4096;
        float hp00=hc[j0*16+s0],hp01=hc[j1*16+s0];
        float hp10=hc[j0*16+s1],hp11=hc[j1*16+s1];

        float xr0=cr0+xv0.x*wxr0.x+xv0.y*wxr0.y+xv0.z*wxr0.z+xv0.w*wxr0.w;
        float xr1=cr1+xv0.x*wxr1.x+xv0.y*wxr1.y+xv0.z*wxr1.z+xv0.w*wxr1.w;
        float xz0=cz0+xv0.x*wxz0.x+xv0.y*wxz0.y+xv0.z*wxz0.z+xv0.w*wxz0.w;
        float xz1=cz1+xv0.x*wxz1.x+xv0.y*wxz1.y+xv0.z*wxz1.z+xv0.w*wxz1.w;
        float xn0=cn0+xv0.x*wxn0.x+xv0.y*wxn0.y+xv0.z*wxn0.z+xv0.w*wxn0.w;
        float xn1=cn1+xv0.x*wxn1.x+xv0.y*wxn1.y+xv0.z*wxn1.z+xv0.w*wxn1.w;
        float r0=sigm(xr0+lo2(aR0)+br0), r1=sigm(xr1+hi2(aR0)+br1);
        float z0=sigm(xz0+lo2(aZ0)+bz0), z1=sigm(xz1+hi2(aZ0)+bz1);
        float n0=tanhf_(xn0+r0*(lo2(aN0)+bn0)), n1=tanhf_(xn1+r1*(hi2(aN0)+bn1));
        float hA0=(1.f-z0)*n0+z0*hp00, hA1=(1.f-z1)*n1+z1*hp01;

        xr0=cr0+xv1.x*wxr0.x+xv1.y*wxr0.y+xv1.z*wxr0.z+xv1.w*wxr0.w;
        xr1=cr1+xv1.x*wxr1.x+xv1.y*wxr1.y+xv1.z*wxr1.z+xv1.w*wxr1.w;
        xz0=cz0+xv1.x*wxz0.x+xv1.y*wxz0.y+xv1.z*wxz0.z+xv1.w*wxz0.w;
        xz1=cz1+xv1.x*wxz1.x+xv1.y*wxz1.y+xv1.z*wxz1.z+xv1.w*wxz1.w;
        xn0=cn0+xv1.x*wxn0.x+xv1.y*wxn0.y+xv1.z*wxn0.z+xv1.w*wxn0.w;
        xn1=cn1+xv1.x*wxn1.x+xv1.y*wxn1.y+xv1.z*wxn1.z+xv1.w*wxn1.w;
        r0=sigm(xr0+lo2(aR1)+br0); r1=sigm(xr1+hi2(aR1)+br1);
        z0=sigm(xz0+lo2(aZ1)+bz0); z1=sigm(xz1+hi2(aZ1)+bz1);
        n0=tanhf_(xn0+r0*(lo2(aN1)+bn0)); n1=tanhf_(xn1+r1*(hi2(aN1)+bn1));
        float hB0=(1.f-z0)*n0+z0*hp10, hB1=(1.f-z1)*n1+z1*hp11;

        // DSMEM h for next step, then arrive (release) and hide globals
        const unsigned nxtb=(unsigned)((cur^1)*16384);
        u64 pj0=pk2(hA0,hB0), pj1=pk2(hA1,hB1);
        #pragma unroll
        for(int r=0;r<4;r++){
            unsigned pb=peer[r]+nxtb;
            stc64(pb+(unsigned)(j0*16+s0)*4,pj0);
            stc64(pb+(unsigned)(j1*16+s0)*4,pj1);
        }
        CARRIVE();
        split_st(g_ab,(size_t)bg0*256+t,dir*256+j0,hA0,hA1);
        split_st(g_ab,(size_t)bg1*256+t,dir*256+j0,hB0,hB1);
        if(t==255){
            *(float2*)&g_h1[(size_t)bg0*512+dir*256+j0]=make_float2(hA0,hA1);
            *(float2*)&g_h1[(size_t)bg1*512+dir*256+j0]=make_float2(hB0,hB1);
        }
        if(s<Tsz-1)CWAIT();
    }
    CWAIT();
}

// ===== W conversion ========================================================
__global__ void convW(const float* __restrict__ Wih1){
    const int n=blockIdx.x, k=threadIdx.x;
    float w=Wih1[(size_t)n*512+k];
    __nv_bfloat16 hi=__float2bfloat16(w);
    __nv_bfloat16 lo=__float2bfloat16(w-__bfloat162float(hi));
    g_bb[(size_t)n*1536+k]=hi;
    g_bb[(size_t)n*1536+512+k]=hi;
    g_bb[(size_t)n*1536+1024+k]=lo;
}

// ===== xp GEMM via wmma bf16 + 3-stage cp.async pipeline ===================
#define LDM 48
__global__ void __launch_bounds__(256,2) xpw(){
    __shared__ __nv_bfloat16 As[3][128][LDM], Bs[3][128][LDM];
    const int bn=blockIdx.x, bm=blockIdx.y;
    const int tid=threadIdx.x, wid=tid>>5;
    const int wm=wid>>1, wnb=wid&1;
    wmma::fragment<wmma::accumulator,16,16,16,float> acc[2][4];
    #pragma unroll
    for(int i=0;i<2;i++)
        #pragma unroll
        for(int j=0;j<4;j++)wmma::fill_fragment(acc[i][j],0.f);

    const int lr=tid>>2, lg=tid&3;
    #define LOADST(st,kc) do{ \
        cpa16(smaddr(&As[st][lr][lg*8]),      &g_ab[(size_t)(bm*128+lr)*1536+(kc)*32+lg*8]); \
        cpa16(smaddr(&As[st][64+lr][lg*8]),   &g_ab[(size_t)(bm*128+64+lr)*1536+(kc)*32+lg*8]); \
        cpa16(smaddr(&Bs[st][lr][lg*8]),      &g_bb[(size_t)(bn*128+lr)*1536+(kc)*32+lg*8]); \
        cpa16(smaddr(&Bs[st][64+lr][lg*8]),   &g_bb[(size_t)(bn*128+64+lr)*1536+(kc)*32+lg*8]); \
        CPCOMMIT(); }while(0)

    LOADST(0,0); LOADST(1,1);
    for(int kc=0;kc<48;kc++){
        const int st=kc%3;
        if(kc<46){
            LOADST((kc+2)%3,kc+2);
            asm volatile("cp.async.wait_group 2;":::"memory");
        }else if(kc==46){
            asm volatile("cp.async.wait_group 1;":::"memory");
        }else{
            asm volatile("cp.async.wait_group 0;":::"memory");
        }
        __syncthreads();
        #pragma unroll
        for(int kk=0;kk<2;kk++){
            wmma::fragment<wmma::matrix_a,16,16,16,__nv_bfloat16,wmma::row_major> af[2];
            wmma::fragment<wmma::matrix_b,16,16,16,__nv_bfloat16,wmma::col_major> bf[4];
            #pragma unroll
            for(int i=0;i<2;i++)wmma::load_matrix_sync(af[i],&As[st][wm*32+i*16][kk*16],LDM);
            #pragma unroll
            for(int j=0;j<4;j++)wmma::load_matrix_sync(bf[j],&Bs[st][wnb*64+j*16][kk*16],LDM);
            #pragma unroll
            for(int i=0;i<2;i++)
                #pragma unroll
                for(int j=0;j<4;j++)wmma::mma_sync(acc[i][j],af[i],bf[j],acc[i][j]);
        }
        __syncthreads();
    }
    #pragma unroll
    for(int i=0;i<2;i++)
        #pragma unroll
        for(int j=0;j<4;j++)
            wmma::store_matrix_sync(&g_xp[(size_t)(bm*128+wm*32+i*16)*768+bn*128+wnb*64+j*16],
                                    acc[i][j],768,wmma::mem_row_major);
}

// ===== layer 1 fwd scan: split barrier + xp prefetch =======================
__global__ void __launch_bounds__(256,1) __cluster_dims__(4,1,1) gru1(
    const float* __restrict__ Whh1,const float* __restrict__ bih1,
    const float* __restrict__ bhh1)
{
    extern __shared__ __align__(16) unsigned char smraw[];
    ulonglong2* wrz=(ulonglong2*)smraw;
    u64* wn=(u64*)(smraw+131072);
    u64* hs2=(u64*)(smraw+196608);
    unsigned q; asm("mov.u32 %0,%%cluster_ctarank;":"=r"(q));
    const int cid=blockIdx.x>>2;
    const int tid=threadIdx.x, w=tid>>5, lane=tid&31;
    const int jp=(lane&7)|((w&3)<<3);
    const int sq=(lane>>3)|((w>>2)<<2);
    const int j0=q*64+2*jp, j1=j0+1;
    const int b=cid*8+sq;

    for(int i=tid;i<8192;i+=256){
        int k=i>>5,p=i&31,jj=q*64+2*p;
        ulonglong2 rz;
        rz.x=pk2(Whh1[(size_t)(0*256+jj)*256+k],Whh1[(size_t)(0*256+jj+1)*256+k]);
        rz.y=pk2(Whh1[(size_t)(1*256+jj)*256+k],Whh1[(size_t)(1*256+jj+1)*256+k]);
        wrz[i]=rz;
        wn[i]=pk2(Whh1[(size_t)(2*256+jj)*256+k],Whh1[(size_t)(2*256+jj+1)*256+k]);
    }
    const float cr0=bih1[j0]+bhh1[j0],         cr1=bih1[j1]+bhh1[j1];
    const float cz0=bih1[256+j0]+bhh1[256+j0], cz1=bih1[256+j1]+bhh1[256+j1];
    const float cx0=bih1[512+j0], cx1=bih1[512+j1];
    const float cn0=bhh1[512+j0], cn1=bhh1[512+j1];

    for(int i=tid;i<4096;i+=256)hs2[i]=0ull;
    unsigned hsa=smaddr(hs2);
    unsigned peer[4];
    #pragma unroll
    for(int r=0;r<4;r++)peer[r]=mapar(hsa,r);
    __syncthreads();
    CSYNC();

    for(int t=0;t<Tsz;t++){
        // prefetch gate rows for this step (consumed after inner loop)
        const float* xr_=&g_xp[(size_t)(b*256+t)*768];
        float2 pr=__ldg((const float2*)(xr_+j0));
        float2 pz=__ldg((const float2*)(xr_+256+j0));
        float2 pn=__ldg((const float2*)(xr_+512+j0));

        const int cur=t&1;
        const u64* hk=hs2+cur*2048;
        u64 aR=0,aZ=0,aN=0;
        #pragma unroll 8
        for(int k=0;k<256;k++){
            u64 hv=hk[k*8+sq];
            ulonglong2 rz=wrz[k*32+jp];
            aR=ffma2(hv,rz.x,aR); aZ=ffma2(hv,rz.y,aZ); aN=ffma2(hv,wn[k*32+jp],aN);
        }
        float hp0=lo2(hk[j0*8+sq]), hp1=lo2(hk[j1*8+sq]);
        float r0=sigm(pr.x+lo2(aR)+cr0), r1=sigm(pr.y+hi2(aR)+cr1);
        float z0=sigm(pz.x+lo2(aZ)+cz0), z1=sigm(pz.y+hi2(aZ)+cz1);
        float n0=tanhf_(pn.x+cx0+r0*(lo2(aN)+cn0));
        float n1=tanhf_(pn.y+cx1+r1*(hi2(aN)+cn1));
        float h0=(1.f-z0)*n0+z0*hp0, h1=(1.f-z1)*n1+z1*hp1;

        const unsigned nxtb=(unsigned)((cur^1)*16384);
        u64 s0=dup2(h0), s1=dup2(h1);
        #pragma unroll
        for(int r=0;r<4;r++){
            unsigned pb=peer[r]+nxtb;
            stc64(pb+(unsigned)(j0*8+sq)*8,s0);
            stc64(pb+(unsigned)(j1*8+sq)*8,s1);
        }
        CARRIVE();
        if(t==255)*(float2*)&g_h2f[b*256+j0]=make_float2(h0,h1);
        if(t<Tsz-1)CWAIT();
    }
    CWAIT();
}

// ===== layer 1 single bwd step (h=0): smem-staged weights ==================
__global__ void __launch_bounds__(256,1) g1bwd(
    const float* __restrict__ Wih1,const float* __restrict__ bih1,
    const float* __restrict__ bhh1)
{
    extern __shared__ __align__(16) u64 ws[];   // [3][512][8 jp] = 98,304 B
    const int bt=blockIdx.x>>4, jt=blockIdx.x&15;
    const int tid=threadIdx.x;
    const float* W=Wih1+(size_t)768*512;

    for(int i=tid;i<3*512*8;i+=256){
        int p=i&7, k=(i>>3)&511, g=i>>12;
        int J0=jt*16+2*p;
        ws[i]=pk2(W[(size_t)(g*256+J0)*512+k],W[(size_t)(g*256+J0+1)*512+k]);
    }
    __syncthreads();

    const int bl=tid>>3, jp=tid&7;
    const int b=bt*32+bl, j0=jt*16+2*jp, j1=j0+1;
    const float2* xp=(const float2*)&g_h1[(size_t)b*512];
    u64 ar=0,az=0,an=0;
    #pragma unroll 8
    for(int k2=0;k2<256;k2++){
        float2 xv=__ldg(&xp[k2]);
        u64 x0=dup2(xv.x),x1=dup2(xv.y);
        ar=ffma2(x0,ws[(size_t)(0*512+2*k2  )*8+jp],ar);
        ar=ffma2(x1,ws[(size_t)(0*512+2*k2+1)*8+jp],ar);
        az=ffma2(x0,ws[(size_t)(1*512+2*k2  )*8+jp],az);
        az=ffma2(x1,ws[(size_t)(1*512+2*k2+1)*8+jp],az);
        an=ffma2(x0,ws[(size_t)(2*512+2*k2  )*8+jp],an);
        an=ffma2(x1,ws[(size_t)(2*512+2*k2+1)*8+jp],an);
    }
    const float* bi=bih1+768; const float* bh=bhh1+768;
    float r0=sigm(lo2(ar)+bi[j0]+bh[j0]);
    float r1=sigm(hi2(ar)+bi[j1]+bh[j1]);
    float z0=sigm(lo2(az)+bi[256+j0]+bh[256+j0]);
    float z1=sigm(hi2(az)+bi[256+j1]+bh[256+j1]);
    float n0=tanhf_(lo2(an)+bi[512+j0]+r0*bh[512+j0]);
    float n1=tanhf_(hi2(an)+bi[512+j1]+r1*bh[512+j1]);
    *(float2*)&g_h2b[b*256+j0]=make_float2((1.f-z0)*n0,(1.f-z1)*n1);
}

// ===== head =====
__global__ void gru_head(const float* __restrict__ W_out,
                         const float* __restrict__ b_out,float* __restrict__ out){
    const int b=blockIdx.x, tid=threadIdx.x;
    float a0=0,a1=0,a2=0;
    for(int k=tid;k<Hsz;k+=128){
        float v=g_h2f[b*Hsz+k]+g_h2b[b*Hsz+k];
        a0+=v*W_out[k];a1+=v*W_out[256+k];a2+=v*W_out[512+k];
    }
    #pragma unroll
    for(int o=16;o>0;o>>=1){
        a0+=__shfl_xor_sync(0xffffffffu,a0,o);
        a1+=__shfl_xor_sync(0xffffffffu,a1,o);
        a2+=__shfl_xor_sync(0xffffffffu,a2,o);
    }
    __shared__ float red[3][4];
    if((tid&31)==0){int w=tid>>5;red[0][w]=a0;red[1][w]=a1;red[2][w]=a2;}
    __syncthreads();
    if(tid==0){
        a0=red[0][0]+red[0][1]+red[0][2]+red[0][3]+b_out[0];
        a1=red[1][0]+red[1][1]+red[1][2]+red[1][3]+b_out[1];
        a2=red[2][0]+red[2][1]+red[2][2]+red[2][3]+b_out[2];
        float m=fmaxf(a0,fmaxf(a1,a2));
        float e0=expf(a0-m),e1=expf(a1-m),e2=expf(a2-m);
        float inv=1.f/(e0+e1+e2);
        out[b*3+0]=e0*inv;out[b*3+1]=e1*inv;out[b*3+2]=e2*inv;
    }
}

extern "C" void kernel_launch(void* const* d_in,const int* in_sizes,int n_in,
                              void* d_out,int out_size){
    const float* x=(const float*)d_in[0];
    const float* Wih0=(const float*)d_in[1];
    const float* Whh0=(const float*)d_in[2];
    const float* bih0=(const float*)d_in[3];
    const float* bhh0=(const float*)d_in[4];
    const float* Wih1=(const float*)d_in[5];
    const float* Whh1=(const float*)d_in[6];
    const float* bih1=(const float*)d_in[7];
    const float* bhh1=(const float*)d_in[8];
    const float* W_out=(const float*)d_in[9];
    const float* b_out=(const float*)d_in[10];
    float* out=(float*)d_out;

    const int sm0=196608+32768;
    const int sm1=196608+32768;
    const int smb=98304;
    cudaFuncSetAttribute(gru0,cudaFuncAttributeMaxDynamicSharedMemorySize,sm0);
    cudaFuncSetAttribute(gru1,cudaFuncAttributeMaxDynamicSharedMemorySize,sm1);
    cudaFuncSetAttribute(g1bwd,cudaFuncAttributeMaxDynamicSharedMemorySize,smb);

    convW<<<768,512>>>(Wih1);
    gru0<<<128,256,sm0>>>(x,Wih0,Whh0,bih0,bhh0);
    xpw<<<dim3(6,512),256>>>();
    g1bwd<<<128,256,smb>>>(Wih1,bih1,bhh1);
    gru1<<<128,256,sm1>>>(Whh1,bih1,bhh1);
    gru_head<<<256,128>>>(W_out,b_out,out);
}